// round 3
// baseline (speedup 1.0000x reference)
#include <cuda_runtime.h>
#include <cuda_bf16.h>
#include <math.h>

#define BB 4
#define LL 2048
#define DD 1024
#define HH 16
#define DH 64
#define NS 16
#define EE 16
#define FF 4096

// ---------------- scratch ----------------
__device__ float g_kh  [BB*LL*DD];
__device__ float g_vh  [BB*LL*DD];
__device__ float g_qh1 [NS*DD];
__device__ float g_att1[BB*NS*DD];
__device__ float g_o   [BB*NS*DD];
__device__ float g_hn  [BB*NS*DD];
__device__ float g_ug  [BB*EE*FF];
__device__ float g_qh2 [BB*LL*DD];
__device__ float g_kh2 [BB*NS*DD];
__device__ float g_vh2 [BB*NS*DD];
__device__ float g_att2[BB*LL*DD];
__device__ float g_sc  [BB*HH*NS*LL];
__device__ float g_part[16*BB*NS*DD];
__device__ float g_skp [8*64*DD];
__device__ float g_w2p [8*BB*EE*DD];

__device__ __forceinline__ unsigned f2tf32(float x) {
    unsigned y;
    asm("cvt.rna.tf32.f32 %0, %1;" : "=r"(y) : "f"(x));
    return y;
}

__device__ __forceinline__ void cpa16(float* dst, const float* src) {
    unsigned d = (unsigned)__cvta_generic_to_shared(dst);
    asm volatile("cp.async.cg.shared.global [%0], [%1], 16;\n" :: "r"(d), "l"(src));
}
__device__ __forceinline__ void cpa_commit() {
    asm volatile("cp.async.commit_group;\n" ::: "memory");
}
__device__ __forceinline__ void cpa_wait1() {
    asm volatile("cp.async.wait_group 1;\n" ::: "memory");
}

__device__ __forceinline__ float4 ldcs4(const float* p) {
    float4 v;
    asm volatile("ld.global.cs.v4.f32 {%0,%1,%2,%3}, [%4];"
                 : "=f"(v.x), "=f"(v.y), "=f"(v.z), "=f"(v.w) : "l"(p));
    return v;
}

// ======================= pipelined TF32 tensor-core GEMM =======================
// C[M,N] = A[M,K] @ W[K,N] + bias[N].  M%128==0, N%128==0, K%32==0.
// 128x128x32 block tile, 256 threads, 3-stage cp.async pipeline.
#define APITCH 36
#define BPITCH 136
#define ASTG (128*APITCH)
#define BSTG (32*BPITCH)

__global__ __launch_bounds__(256)
void gemm_tf32(const float* __restrict__ A, const float* __restrict__ W,
               const float* __restrict__ bias, float* __restrict__ C,
               int M, int N, int K)
{
    extern __shared__ float smp[];
    float* As = smp;                 // [3][128][APITCH]
    float* Bs = smp + 3 * ASTG;      // [3][32][BPITCH]

    const int tid  = threadIdx.x;
    const int wid  = tid >> 5;
    const int lane = tid & 31;
    const int g    = lane >> 2;
    const int tig  = lane & 3;
    const int wm0  = (wid >> 2) * 64;
    const int wn0  = (wid & 3) * 32;
    const int row0 = blockIdx.y * 128;
    const int col0 = blockIdx.x * 128;

    const int am = tid >> 3;          // 0..31 (+32/pass)
    const int ak = (tid & 7) * 4;
    const int bk = tid >> 5;          // 0..7 (+8/pass)
    const int bn = (tid & 31) * 4;

    const int NT = K >> 5;

    // stage loader
    auto load_stage = [&](int tile, int st) {
        const int k0 = tile * 32;
        float* as = As + st * ASTG;
        float* bs = Bs + st * BSTG;
#pragma unroll
        for (int p = 0; p < 4; p++) {
            int m = am + p * 32;
            cpa16(&as[m * APITCH + ak], &A[(size_t)(row0 + m) * K + k0 + ak]);
            int kb = bk + p * 8;
            cpa16(&bs[kb * BPITCH + bn], &W[(size_t)(k0 + kb) * N + col0 + bn]);
        }
    };

    float acc[4][4][4];
#pragma unroll
    for (int i = 0; i < 4; i++)
#pragma unroll
        for (int j = 0; j < 4; j++)
#pragma unroll
            for (int c = 0; c < 4; c++) acc[i][j][c] = 0.f;

    load_stage(0, 0); cpa_commit();
    load_stage(1, 1); cpa_commit();

    int st = 0;
    for (int i = 0; i < NT; i++) {
        cpa_wait1();
        __syncthreads();

        const float* asf = As + st * ASTG;
        const float* bsf = Bs + st * BSTG;
#pragma unroll
        for (int kk = 0; kk < 4; kk++) {
            unsigned af[4][4];
#pragma unroll
            for (int mt = 0; mt < 4; mt++) {
                int mb = wm0 + mt * 16;
                af[mt][0] = f2tf32(asf[(mb + g    ) * APITCH + kk * 8 + tig]);
                af[mt][1] = f2tf32(asf[(mb + 8 + g) * APITCH + kk * 8 + tig]);
                af[mt][2] = f2tf32(asf[(mb + g    ) * APITCH + kk * 8 + tig + 4]);
                af[mt][3] = f2tf32(asf[(mb + 8 + g) * APITCH + kk * 8 + tig + 4]);
            }
            unsigned bf[4][2];
#pragma unroll
            for (int nt = 0; nt < 4; nt++) {
                bf[nt][0] = f2tf32(bsf[(kk * 8 + tig    ) * BPITCH + wn0 + nt * 8 + g]);
                bf[nt][1] = f2tf32(bsf[(kk * 8 + tig + 4) * BPITCH + wn0 + nt * 8 + g]);
            }
#pragma unroll
            for (int mt = 0; mt < 4; mt++)
#pragma unroll
                for (int nt = 0; nt < 4; nt++) {
                    asm volatile(
                        "mma.sync.aligned.m16n8k8.row.col.f32.tf32.tf32.f32 "
                        "{%0,%1,%2,%3}, {%4,%5,%6,%7}, {%8,%9}, {%0,%1,%2,%3};\n"
                        : "+f"(acc[mt][nt][0]), "+f"(acc[mt][nt][1]),
                          "+f"(acc[mt][nt][2]), "+f"(acc[mt][nt][3])
                        : "r"(af[mt][0]), "r"(af[mt][1]), "r"(af[mt][2]), "r"(af[mt][3]),
                          "r"(bf[nt][0]), "r"(bf[nt][1]));
                }
        }

        if (i + 2 < NT) load_stage(i + 2, (st + 2) % 3);
        cpa_commit();
        st = (st + 1) % 3;
    }

#pragma unroll
    for (int mt = 0; mt < 4; mt++) {
#pragma unroll
        for (int nt = 0; nt < 4; nt++) {
            int r = row0 + wm0 + mt * 16 + g;
            int c = col0 + wn0 + nt * 8 + tig * 2;
            float b0v = bias[c], b1v = bias[c + 1];
            float2 v0 = make_float2(acc[mt][nt][0] + b0v, acc[mt][nt][1] + b1v);
            float2 v1 = make_float2(acc[mt][nt][2] + b0v, acc[mt][nt][3] + b1v);
            *(float2*)&C[(size_t)r * N + c] = v0;
            *(float2*)&C[(size_t)(r + 8) * N + c] = v1;
        }
    }
}
#define GEMM_SMEM (3 * (ASTG + BSTG) * 4)

// ======================= skinny split-K GEMM (M<=64) =======================
template<int M>
__global__ void gemm_skinny(const float* __restrict__ A, const float* __restrict__ W,
                            float* __restrict__ part, int N, int K)
{
    __shared__ float As[64][132];
    const int tid = threadIdx.x;
    const int ks = blockIdx.y;
    const int n  = blockIdx.x * 64 + (tid & 63);
    const int mg = tid >> 6;
    const int k0 = ks * 128;

    for (int idx = tid; idx < M * 32; idx += 256) {
        int m = idx >> 5, c4 = (idx & 31) * 4;
        *(float4*)&As[m][c4] = *(const float4*)&A[(size_t)m * K + k0 + c4];
    }
    __syncthreads();

    const int MR = M / 4;
    float acc[MR];
#pragma unroll
    for (int r = 0; r < MR; r++) acc[r] = 0.f;

#pragma unroll 4
    for (int k = 0; k < 128; k++) {
        float wv = __ldg(&W[(size_t)(k0 + k) * N + n]);
#pragma unroll
        for (int r = 0; r < MR; r++) acc[r] += As[mg + 4 * r][k] * wv;
    }
#pragma unroll
    for (int r = 0; r < MR; r++)
        part[((size_t)ks * 64 + mg + 4 * r) * N + n] = acc[r];
}

__global__ void skinny_reduce(const float* __restrict__ part, const float* __restrict__ bias,
                              float* __restrict__ C, int M, int N)
{
    int i = blockIdx.x * 256 + threadIdx.x;
    if (i < M * N) {
        int n = i & (N - 1);
        int m = i / N;
        float s = bias[n];
#pragma unroll
        for (int z = 0; z < 8; z++) s += part[((size_t)z * 64 + m) * N + n];
        C[i] = s;
    }
}

// skinny reduce + add slot_query residual (for dispatch output projection)
__global__ void skinny_reduce_addsq(const float* __restrict__ part, const float* __restrict__ bias,
                                    const float* __restrict__ sq, float* __restrict__ C)
{
    int i = blockIdx.x * 256 + threadIdx.x;   // 64*DD
    int n = i & (DD - 1);
    int m = i / DD;
    float s = bias[n] + sq[i % (NS * DD)];
#pragma unroll
    for (int z = 0; z < 8; z++) s += part[((size_t)z * 64 + m) * DD + n];
    C[i] = s;
}

// ======================= dispatch attention =======================
__global__ void disp_scores(const float* __restrict__ qh, const float* __restrict__ kh,
                            float* __restrict__ sc)
{
    __shared__ float q[16][64];
    __shared__ float kt[128][65];
    const int j0 = blockIdx.x * 128;
    const int h  = blockIdx.y;
    const int b  = blockIdx.z;
    const int tid = threadIdx.x;

    for (int i = tid; i < NS * DH; i += 256) {
        int s = i >> 6, d = i & 63;
        q[s][d] = qh[(size_t)s * DD + h * DH + d];
    }
#pragma unroll
    for (int p = 0; p < 8; p++) {
        int idx = tid + p * 256;
        int jj = idx >> 4, d4 = (idx & 15) * 4;
        float4 v = *(const float4*)&kh[((size_t)b * LL + j0 + jj) * DD + h * DH + d4];
        kt[jj][d4 + 0] = v.x; kt[jj][d4 + 1] = v.y;
        kt[jj][d4 + 2] = v.z; kt[jj][d4 + 3] = v.w;
    }
    __syncthreads();

#pragma unroll
    for (int p = 0; p < 8; p++) {
        int idx = tid + p * 256;
        int s = idx >> 7, jj = idx & 127;
        float dot = 0.f;
#pragma unroll
        for (int d = 0; d < DH; d++) dot += q[s][d] * kt[jj][d];
        sc[(((size_t)b * HH + h) * NS + s) * LL + j0 + jj] = dot * 0.125f;
    }
}

__global__ void disp_softmax(float* __restrict__ sc)
{
    __shared__ float red[9];
    const int tid = threadIdx.x;
    float* r = sc + (size_t)blockIdx.x * LL;
    float v[8];
    float mx = -1e30f;
#pragma unroll
    for (int i = 0; i < 8; i++) { v[i] = r[tid + i * 256]; mx = fmaxf(mx, v[i]); }
#pragma unroll
    for (int o = 16; o; o >>= 1) mx = fmaxf(mx, __shfl_xor_sync(0xffffffffu, mx, o));
    int wd = tid >> 5, ln = tid & 31;
    if (!ln) red[wd] = mx;
    __syncthreads();
    if (tid < 32) {
        mx = (ln < 8) ? red[ln] : -1e30f;
#pragma unroll
        for (int o = 4; o; o >>= 1) mx = fmaxf(mx, __shfl_xor_sync(0xffffffffu, mx, o));
        if (!ln) red[8] = mx;
    }
    __syncthreads();
    mx = red[8];
    float sum = 0.f;
#pragma unroll
    for (int i = 0; i < 8; i++) { v[i] = __expf(v[i] - mx); sum += v[i]; }
#pragma unroll
    for (int o = 16; o; o >>= 1) sum += __shfl_xor_sync(0xffffffffu, sum, o);
    __syncthreads();
    if (!ln) red[wd] = sum;
    __syncthreads();
    if (tid < 32) {
        sum = (ln < 8) ? red[ln] : 0.f;
#pragma unroll
        for (int o = 4; o; o >>= 1) sum += __shfl_xor_sync(0xffffffffu, sum, o);
        if (!ln) red[8] = sum;
    }
    __syncthreads();
    float inv = 1.f / red[8];
#pragma unroll
    for (int i = 0; i < 8; i++) r[tid + i * 256] = v[i] * inv;
}

__global__ void disp_av(const float* __restrict__ sc, const float* __restrict__ vh,
                        float* __restrict__ part)
{
    __shared__ float p[16][132];
    __shared__ float vt[128][65];
    const int h = blockIdx.x, b = blockIdx.y, jz = blockIdx.z;
    const int j0 = jz * 128;
    const int tid = threadIdx.x;

#pragma unroll
    for (int q = 0; q < 2; q++) {
        int idx = tid + q * 256;
        int s = idx >> 5, j4 = (idx & 31) * 4;
        float4 v = *(const float4*)&sc[(((size_t)b * HH + h) * NS + s) * LL + j0 + j4];
        *(float4*)&p[s][j4] = v;
    }
#pragma unroll
    for (int q = 0; q < 8; q++) {
        int idx = tid + q * 256;
        int jj = idx >> 4, d4 = (idx & 15) * 4;
        float4 v = *(const float4*)&vh[((size_t)b * LL + j0 + jj) * DD + h * DH + d4];
        vt[jj][d4 + 0] = v.x; vt[jj][d4 + 1] = v.y;
        vt[jj][d4 + 2] = v.z; vt[jj][d4 + 3] = v.w;
    }
    __syncthreads();

    float acc[4] = {0.f, 0.f, 0.f, 0.f};
#pragma unroll 4
    for (int jj = 0; jj < 128; jj++) {
#pragma unroll
        for (int k = 0; k < 4; k++) {
            int idx = tid + k * 256;
            int s = idx >> 6, d = idx & 63;
            acc[k] += p[s][jj] * vt[jj][d];
        }
    }
#pragma unroll
    for (int k = 0; k < 4; k++) {
        int idx = tid + k * 256;
        int s = idx >> 6, d = idx & 63;
        part[(size_t)jz * (BB * NS * DD) + ((size_t)b * NS + s) * DD + h * DH + d] = acc[k];
    }
}

__global__ void disp_reduce(const float* __restrict__ part, float* __restrict__ att1)
{
    int i = blockIdx.x * 256 + threadIdx.x;
    float s = 0.f;
#pragma unroll
    for (int z = 0; z < 16; z++) s += part[(size_t)z * (BB * NS * DD) + i];
    att1[i] = s;
}

// ---------------- layernorm ----------------
__global__ void ln_kernel(const float* __restrict__ inp, const float* __restrict__ gam,
                          const float* __restrict__ bet, float* __restrict__ outp)
{
    const int row = blockIdx.x;
    const int e = row & (NS - 1);
    const float* xr = inp + (size_t)row * DD;
    __shared__ float r1[8], r2[8];
    float s1 = 0.f, s2 = 0.f;
    for (int d = threadIdx.x; d < DD; d += 256) {
        float v = xr[d];
        s1 += v; s2 += v * v;
    }
#pragma unroll
    for (int o = 16; o; o >>= 1) {
        s1 += __shfl_xor_sync(0xffffffffu, s1, o);
        s2 += __shfl_xor_sync(0xffffffffu, s2, o);
    }
    int wid = threadIdx.x >> 5, lane = threadIdx.x & 31;
    if (!lane) { r1[wid] = s1; r2[wid] = s2; }
    __syncthreads();
    if (threadIdx.x < 32) {
        s1 = (lane < 8) ? r1[lane] : 0.f;
        s2 = (lane < 8) ? r2[lane] : 0.f;
#pragma unroll
        for (int o = 4; o; o >>= 1) {
            s1 += __shfl_xor_sync(0xffffffffu, s1, o);
            s2 += __shfl_xor_sync(0xffffffffu, s2, o);
        }
        if (!lane) { r1[0] = s1; r2[0] = s2; }
    }
    __syncthreads();
    float mu  = r1[0] * (1.f / DD);
    float var = r2[0] * (1.f / DD) - mu * mu;
    float inv = rsqrtf(var + 1e-5f);
    for (int d = threadIdx.x; d < DD; d += 256)
        outp[(size_t)row * DD + d] = (xr[d] - mu) * inv * gam[(size_t)e * DD + d] + bet[(size_t)e * DD + d];
}

__device__ __forceinline__ float silu_f(float x) { return x / (1.f + __expf(-x)); }

// ---------------- expert up/gate (float4, streaming) ----------------
// grid (FF/512, E), 128 threads; thread covers 4 consecutive f
__global__ void expert_ug(const float* __restrict__ hn,
                          const float* __restrict__ W1, const float* __restrict__ b1,
                          const float* __restrict__ Wg, const float* __restrict__ bg,
                          float* __restrict__ ug)
{
    const int e = blockIdx.y;
    const int f = blockIdx.x * 512 + threadIdx.x * 4;
    __shared__ float hs[BB][DD];
    for (int i = threadIdx.x; i < BB * DD / 4; i += 128) {
        int b = (i * 4) >> 10, d4 = (i * 4) & 1023;
        *(float4*)&hs[b][d4] = *(const float4*)&hn[((size_t)b * NS + e) * DD + d4];
    }
    __syncthreads();

    const float* w1 = W1 + (size_t)e * DD * FF + f;
    const float* wg = Wg + (size_t)e * DD * FF + f;
    float au[BB][4], ag[BB][4];
#pragma unroll
    for (int b = 0; b < BB; b++)
#pragma unroll
        for (int j = 0; j < 4; j++) { au[b][j] = 0.f; ag[b][j] = 0.f; }

#pragma unroll 4
    for (int d = 0; d < DD; d++) {
        float4 w1v = ldcs4(&w1[(size_t)d * FF]);
        float4 wgv = ldcs4(&wg[(size_t)d * FF]);
#pragma unroll
        for (int b = 0; b < BB; b++) {
            float hv = hs[b][d];
            au[b][0] += hv * w1v.x; au[b][1] += hv * w1v.y;
            au[b][2] += hv * w1v.z; au[b][3] += hv * w1v.w;
            ag[b][0] += hv * wgv.x; ag[b][1] += hv * wgv.y;
            ag[b][2] += hv * wgv.z; ag[b][3] += hv * wgv.w;
        }
    }
    float4 bu = *(const float4*)&b1[(size_t)e * FF + f];
    float4 bv = *(const float4*)&bg[(size_t)e * FF + f];
#pragma unroll
    for (int b = 0; b < BB; b++) {
        float4 r;
        r.x = silu_f(au[b][0] + bu.x) * silu_f(ag[b][0] + bv.x);
        r.y = silu_f(au[b][1] + bu.y) * silu_f(ag[b][1] + bv.y);
        r.z = silu_f(au[b][2] + bu.z) * silu_f(ag[b][2] + bv.z);
        r.w = silu_f(au[b][3] + bu.w) * silu_f(ag[b][3] + bv.w);
        *(float4*)&ug[((size_t)b * EE + e) * FF + f] = r;
    }
}

// ---------------- expert down: split-F partials (float4, streaming) ----------------
// grid (DD/512, E, 8), 128 threads
__global__ void expert_w2p(const float* __restrict__ ug, const float* __restrict__ W2,
                           float* __restrict__ part)
{
    __shared__ float us[BB][512];
    const int e = blockIdx.y, fz = blockIdx.z;
    const int d = blockIdx.x * 512 + threadIdx.x * 4;
    for (int i = threadIdx.x; i < BB * 512 / 4; i += 128) {
        int b = (i * 4) >> 9, f4 = (i * 4) & 511;
        *(float4*)&us[b][f4] = *(const float4*)&ug[((size_t)b * EE + e) * FF + fz * 512 + f4];
    }
    __syncthreads();
    const float* w = W2 + ((size_t)e * FF + fz * 512) * DD + d;
    float acc[BB][4];
#pragma unroll
    for (int b = 0; b < BB; b++)
#pragma unroll
        for (int j = 0; j < 4; j++) acc[b][j] = 0.f;

#pragma unroll 4
    for (int f = 0; f < 512; f++) {
        float4 wv = ldcs4(&w[(size_t)f * DD]);
#pragma unroll
        for (int b = 0; b < BB; b++) {
            float uv = us[b][f];
            acc[b][0] += uv * wv.x; acc[b][1] += uv * wv.y;
            acc[b][2] += uv * wv.z; acc[b][3] += uv * wv.w;
        }
    }
#pragma unroll
    for (int b = 0; b < BB; b++)
        *(float4*)&part[(size_t)fz * (BB * EE * DD) + ((size_t)b * EE + e) * DD + d] =
            make_float4(acc[b][0], acc[b][1], acc[b][2], acc[b][3]);
}

__global__ void w2_reduce(const float* __restrict__ part, const float* __restrict__ b2,
                          float* __restrict__ o)
{
    int i = blockIdx.x * 256 + threadIdx.x;
    int d = i & 1023;
    int e = (i >> 10) & 15;
    float s = b2[(size_t)e * DD + d];
#pragma unroll
    for (int z = 0; z < 8; z++) s += part[(size_t)z * (BB * EE * DD) + i];
    o[i] += s;
}

// ---------------- combine attention ----------------
__global__ void combine_attn(const float* __restrict__ qh, const float* __restrict__ kh,
                             const float* __restrict__ vh, float* __restrict__ out)
{
    extern __shared__ float sm[];
    const int PITCH = HH * 65;
    float* qsm = sm;
    float* ksm = sm + 16 * PITCH;
    float* vsm = sm + 32 * PITCH;
    const int b  = blockIdx.y;
    const int t0 = blockIdx.x * 16;
    const int tid = threadIdx.x;

    for (int i = tid; i < NS * DD; i += 256) {
        int r = i >> 10, hd = i & 1023;
        int h = hd >> 6, d = hd & 63;
        int sw = r * PITCH + h * 65 + d;
        ksm[sw] = kh[(size_t)b * NS * DD + i];
        vsm[sw] = vh[(size_t)b * NS * DD + i];
        qsm[sw] = qh[((size_t)b * LL + t0) * DD + i];
    }
    __syncthreads();

    const int tt = tid >> 4;
    const int h  = tid & 15;

    float qreg[DH];
#pragma unroll
    for (int d = 0; d < DH; d++) qreg[d] = qsm[tt * PITCH + h * 65 + d];

    float sco[NS];
    float mx = -1e30f;
#pragma unroll
    for (int s = 0; s < NS; s++) {
        const float* kp = &ksm[s * PITCH + h * 65];
        float dot = 0.f;
#pragma unroll
        for (int d = 0; d < DH; d++) dot += qreg[d] * kp[d];
        dot *= 0.125f;
        sco[s] = dot;
        mx = fmaxf(mx, dot);
    }
    float sum = 0.f;
#pragma unroll
    for (int s = 0; s < NS; s++) { sco[s] = __expf(sco[s] - mx); sum += sco[s]; }
    float inv = 1.f / sum;

    float ov[DH];
#pragma unroll
    for (int d = 0; d < DH; d++) ov[d] = 0.f;
#pragma unroll
    for (int s = 0; s < NS; s++) {
        float pr = sco[s] * inv;
        const float* vp = &vsm[s * PITCH + h * 65];
#pragma unroll
        for (int d = 0; d < DH; d++) ov[d] += pr * vp[d];
    }
    __syncthreads();
#pragma unroll
    for (int d = 0; d < DH; d++) qsm[tt * PITCH + h * 65 + d] = ov[d];
    __syncthreads();
    for (int i = tid; i < NS * DD; i += 256) {
        int r = i >> 10, hd = i & 1023;
        int hh = hd >> 6, d = hd & 63;
        out[((size_t)b * LL + t0) * DD + i] = qsm[r * PITCH + hh * 65 + d];
    }
}

// ---------------- host launch ----------------
extern "C" void kernel_launch(void* const* d_in, const int* in_sizes, int n_in,
                              void* d_out, int out_size)
{
    const float* x    = (const float*)d_in[0];
    const float* sq   = (const float*)d_in[1];
    const float* dWq  = (const float*)d_in[2];
    const float* dWk  = (const float*)d_in[3];
    const float* dWv  = (const float*)d_in[4];
    const float* dWo  = (const float*)d_in[5];
    const float* dbq  = (const float*)d_in[6];
    const float* dbk  = (const float*)d_in[7];
    const float* dbv  = (const float*)d_in[8];
    const float* dbo  = (const float*)d_in[9];
    const float* cWq  = (const float*)d_in[10];
    const float* cWk  = (const float*)d_in[11];
    const float* cWv  = (const float*)d_in[12];
    const float* cWo  = (const float*)d_in[13];
    const float* cbq  = (const float*)d_in[14];
    const float* cbk  = (const float*)d_in[15];
    const float* cbv  = (const float*)d_in[16];
    const float* cbo  = (const float*)d_in[17];
    const float* elng = (const float*)d_in[18];
    const float* elnb = (const float*)d_in[19];
    const float* eW1  = (const float*)d_in[20];
    const float* eb1  = (const float*)d_in[21];
    const float* eWg  = (const float*)d_in[22];
    const float* ebg  = (const float*)d_in[23];
    const float* eW2  = (const float*)d_in[24];
    const float* eb2  = (const float*)d_in[25];
    float* out = (float*)d_out;

    float *kh, *vh, *qh1, *att1, *o, *hn, *ug, *qh2, *kh2, *vh2, *att2;
    float *sc, *avp, *skp, *w2p;
    cudaGetSymbolAddress((void**)&kh,   g_kh);
    cudaGetSymbolAddress((void**)&vh,   g_vh);
    cudaGetSymbolAddress((void**)&qh1,  g_qh1);
    cudaGetSymbolAddress((void**)&att1, g_att1);
    cudaGetSymbolAddress((void**)&o,    g_o);
    cudaGetSymbolAddress((void**)&hn,   g_hn);
    cudaGetSymbolAddress((void**)&ug,   g_ug);
    cudaGetSymbolAddress((void**)&qh2,  g_qh2);
    cudaGetSymbolAddress((void**)&kh2,  g_kh2);
    cudaGetSymbolAddress((void**)&vh2,  g_vh2);
    cudaGetSymbolAddress((void**)&att2, g_att2);
    cudaGetSymbolAddress((void**)&sc,   g_sc);
    cudaGetSymbolAddress((void**)&avp,  g_part);
    cudaGetSymbolAddress((void**)&skp,  g_skp);
    cudaGetSymbolAddress((void**)&w2p,  g_w2p);

    const int SMEM_COMB = 3 * 16 * (HH * 65) * 4;
    cudaFuncSetAttribute(combine_attn, cudaFuncAttributeMaxDynamicSharedMemorySize, SMEM_COMB);
    cudaFuncSetAttribute(gemm_tf32, cudaFuncAttributeMaxDynamicSharedMemorySize, GEMM_SMEM);

    dim3 gBig(DD / 128, (BB * LL) / 128);
    dim3 gSk(DD / 64, 8);

    // (launch order: 4th launch = gemm_tf32 so ncu profiles the big GEMM)
    gemm_skinny<16><<<gSk, 256>>>(sq, dWq, skp, DD, DD);                       // 1
    skinny_reduce<<<(16 * DD) / 256, 256>>>(skp, dbq, qh1, 16, DD);            // 2
    gemm_tf32<<<gBig, 256, GEMM_SMEM>>>(x, dWk, dbk, kh, BB * LL, DD, DD);     // 3
    gemm_tf32<<<gBig, 256, GEMM_SMEM>>>(x, dWv, dbv, vh, BB * LL, DD, DD);     // 4 <- profiled
    gemm_tf32<<<gBig, 256, GEMM_SMEM>>>(x, cWq, cbq, qh2, BB * LL, DD, DD);    // 5

    // dispatch attention
    disp_scores<<<dim3(LL / 128, HH, BB), 256>>>(qh1, kh, sc);
    disp_softmax<<<BB * HH * NS, 256>>>(sc);
    disp_av<<<dim3(HH, BB, 16), 256>>>(sc, vh, avp);
    disp_reduce<<<(BB * NS * DD) / 256, 256>>>(avp, att1);

    // dispatch output projection + residual (fused)
    gemm_skinny<64><<<gSk, 256>>>(att1, dWo, skp, DD, DD);
    skinny_reduce_addsq<<<(64 * DD) / 256, 256>>>(skp, dbo, sq, o);

    // experts
    ln_kernel<<<BB * NS, 256>>>(o, elng, elnb, hn);
    expert_ug<<<dim3(FF / 512, EE), 128>>>(hn, eW1, eb1, eWg, ebg, ug);
    expert_w2p<<<dim3(DD / 512, EE, 8), 128>>>(ug, eW2, w2p);
    w2_reduce<<<(BB * EE * DD) / 256, 256>>>(w2p, eb2, o);

    // combine projections
    gemm_skinny<64><<<gSk, 256>>>(o, cWk, skp, DD, DD);
    skinny_reduce<<<(64 * DD) / 256, 256>>>(skp, cbk, kh2, 64, DD);
    gemm_skinny<64><<<gSk, 256>>>(o, cWv, skp, DD, DD);
    skinny_reduce<<<(64 * DD) / 256, 256>>>(skp, cbv, vh2, 64, DD);

    // combine attention + final projection
    combine_attn<<<dim3(LL / 16, BB), 256, SMEM_COMB>>>(qh2, kh2, vh2, att2);
    gemm_tf32<<<gBig, 256, GEMM_SMEM>>>(att2, cWo, cbo, out, BB * LL, DD, DD);
}

// round 4
// speedup vs baseline: 1.2388x; 1.2388x over previous
#include <cuda_runtime.h>
#include <cuda_bf16.h>
#include <math.h>

#define BB 4
#define LL 2048
#define DD 1024
#define HH 16
#define DH 64
#define NS 16
#define EE 16
#define FF 4096

// ---------------- scratch ----------------
__device__ float g_kh  [BB*LL*DD];
__device__ float g_vh  [BB*LL*DD];
__device__ float g_qh1 [NS*DD];
__device__ float g_att1[BB*NS*DD];
__device__ float g_o   [BB*NS*DD];
__device__ float g_hn  [BB*NS*DD];
__device__ float g_ug  [BB*EE*FF];
__device__ float g_qh2 [BB*LL*DD];
__device__ float g_kh2 [BB*NS*DD];
__device__ float g_vh2 [BB*NS*DD];
__device__ float g_att2[BB*LL*DD];
__device__ float g_sc  [BB*HH*NS*LL];
__device__ float g_part[16*BB*NS*DD];
__device__ float g_skp [8*64*DD];
__device__ float g_w2p [8*BB*EE*DD];
__device__ float g_xtf [BB*LL*DD];     // x rounded to tf32
__device__ float g_wtf [4*DD*DD];      // dWk,dWv,cWq,cWo rounded to tf32

__device__ __forceinline__ float f2tf32f(float x) {
    unsigned y;
    asm("cvt.rna.tf32.f32 %0, %1;" : "=r"(y) : "f"(x));
    return __uint_as_float(y);
}

__device__ __forceinline__ void cpa16(float* dst, const float* src) {
    unsigned d = (unsigned)__cvta_generic_to_shared(dst);
    asm volatile("cp.async.cg.shared.global [%0], [%1], 16;\n" :: "r"(d), "l"(src));
}
__device__ __forceinline__ void cpa_commit() {
    asm volatile("cp.async.commit_group;\n" ::: "memory");
}
__device__ __forceinline__ void cpa_wait1() {
    asm volatile("cp.async.wait_group 1;\n" ::: "memory");
}

__device__ __forceinline__ float ldcs(const float* p) {
    float v;
    asm volatile("ld.global.cs.f32 %0, [%1];" : "=f"(v) : "l"(p));
    return v;
}

// ---------------- tf32 rounding pre-pass ----------------
__global__ void cvt_tf32(const float* __restrict__ src, float* __restrict__ dst, int n4)
{
    int i = blockIdx.x * 256 + threadIdx.x;
    if (i < n4) {
        float4 v = *(const float4*)&src[i * 4];
        v.x = f2tf32f(v.x); v.y = f2tf32f(v.y);
        v.z = f2tf32f(v.z); v.w = f2tf32f(v.w);
        *(float4*)&dst[i * 4] = v;
    }
}

// ======================= pipelined TF32 tensor-core GEMM =======================
// Inputs pre-rounded to tf32. C[M,N] = A@W + bias. 128x128x32 tile, 3-stage cp.async.
#define APITCH 36
#define BPITCH 136
#define ASTG (128*APITCH)
#define BSTG (32*BPITCH)

__global__ __launch_bounds__(256)
void gemm_tf32(const float* __restrict__ A, const float* __restrict__ W,
               const float* __restrict__ bias, float* __restrict__ C,
               int M, int N, int K)
{
    extern __shared__ float smp[];
    float* As = smp;
    float* Bs = smp + 3 * ASTG;

    const int tid  = threadIdx.x;
    const int wid  = tid >> 5;
    const int lane = tid & 31;
    const int g    = lane >> 2;
    const int tig  = lane & 3;
    const int wm0  = (wid >> 2) * 64;
    const int wn0  = (wid & 3) * 32;
    const int row0 = blockIdx.y * 128;
    const int col0 = blockIdx.x * 128;

    const int am = tid >> 3;
    const int ak = (tid & 7) * 4;
    const int bk = tid >> 5;
    const int bn = (tid & 31) * 4;

    const int NT = K >> 5;

    auto load_stage = [&](int tile, int st) {
        const int k0 = tile * 32;
        float* as = As + st * ASTG;
        float* bs = Bs + st * BSTG;
#pragma unroll
        for (int p = 0; p < 4; p++) {
            int m = am + p * 32;
            cpa16(&as[m * APITCH + ak], &A[(size_t)(row0 + m) * K + k0 + ak]);
            int kb = bk + p * 8;
            cpa16(&bs[kb * BPITCH + bn], &W[(size_t)(k0 + kb) * N + col0 + bn]);
        }
    };

    float acc[4][4][4];
#pragma unroll
    for (int i = 0; i < 4; i++)
#pragma unroll
        for (int j = 0; j < 4; j++)
#pragma unroll
            for (int c = 0; c < 4; c++) acc[i][j][c] = 0.f;

    load_stage(0, 0); cpa_commit();
    load_stage(1, 1); cpa_commit();

    int st = 0;
    for (int i = 0; i < NT; i++) {
        cpa_wait1();
        __syncthreads();

        const float* asf = As + st * ASTG;
        const float* bsf = Bs + st * BSTG;
#pragma unroll
        for (int kk = 0; kk < 4; kk++) {
            unsigned af[4][4];
#pragma unroll
            for (int mt = 0; mt < 4; mt++) {
                int mb = wm0 + mt * 16;
                af[mt][0] = __float_as_uint(asf[(mb + g    ) * APITCH + kk * 8 + tig]);
                af[mt][1] = __float_as_uint(asf[(mb + 8 + g) * APITCH + kk * 8 + tig]);
                af[mt][2] = __float_as_uint(asf[(mb + g    ) * APITCH + kk * 8 + tig + 4]);
                af[mt][3] = __float_as_uint(asf[(mb + 8 + g) * APITCH + kk * 8 + tig + 4]);
            }
            unsigned bf[4][2];
#pragma unroll
            for (int nt = 0; nt < 4; nt++) {
                bf[nt][0] = __float_as_uint(bsf[(kk * 8 + tig    ) * BPITCH + wn0 + nt * 8 + g]);
                bf[nt][1] = __float_as_uint(bsf[(kk * 8 + tig + 4) * BPITCH + wn0 + nt * 8 + g]);
            }
#pragma unroll
            for (int mt = 0; mt < 4; mt++)
#pragma unroll
                for (int nt = 0; nt < 4; nt++) {
                    asm volatile(
                        "mma.sync.aligned.m16n8k8.row.col.f32.tf32.tf32.f32 "
                        "{%0,%1,%2,%3}, {%4,%5,%6,%7}, {%8,%9}, {%0,%1,%2,%3};\n"
                        : "+f"(acc[mt][nt][0]), "+f"(acc[mt][nt][1]),
                          "+f"(acc[mt][nt][2]), "+f"(acc[mt][nt][3])
                        : "r"(af[mt][0]), "r"(af[mt][1]), "r"(af[mt][2]), "r"(af[mt][3]),
                          "r"(bf[nt][0]), "r"(bf[nt][1]));
                }
        }

        if (i + 2 < NT) { load_stage(i + 2, (st + 2) % 3); }
        cpa_commit();
        st = (st + 1) % 3;
    }

#pragma unroll
    for (int mt = 0; mt < 4; mt++) {
#pragma unroll
        for (int nt = 0; nt < 4; nt++) {
            int r = row0 + wm0 + mt * 16 + g;
            int c = col0 + wn0 + nt * 8 + tig * 2;
            float b0v = bias[c], b1v = bias[c + 1];
            float2 v0 = make_float2(acc[mt][nt][0] + b0v, acc[mt][nt][1] + b1v);
            float2 v1 = make_float2(acc[mt][nt][2] + b0v, acc[mt][nt][3] + b1v);
            *(float2*)&C[(size_t)r * N + c] = v0;
            *(float2*)&C[(size_t)(r + 8) * N + c] = v1;
        }
    }
}
#define GEMM_SMEM (3 * (ASTG + BSTG) * 4)

// ======================= skinny split-K GEMM (M<=64) =======================
template<int M>
__global__ void gemm_skinny(const float* __restrict__ A, const float* __restrict__ W,
                            float* __restrict__ part, int N, int K)
{
    __shared__ float As[64][132];
    const int tid = threadIdx.x;
    const int ks = blockIdx.y;
    const int n  = blockIdx.x * 64 + (tid & 63);
    const int mg = tid >> 6;
    const int k0 = ks * 128;

    for (int idx = tid; idx < M * 32; idx += 256) {
        int m = idx >> 5, c4 = (idx & 31) * 4;
        *(float4*)&As[m][c4] = *(const float4*)&A[(size_t)m * K + k0 + c4];
    }
    __syncthreads();

    const int MR = M / 4;
    float acc[MR];
#pragma unroll
    for (int r = 0; r < MR; r++) acc[r] = 0.f;

#pragma unroll 4
    for (int k = 0; k < 128; k++) {
        float wv = __ldg(&W[(size_t)(k0 + k) * N + n]);
#pragma unroll
        for (int r = 0; r < MR; r++) acc[r] += As[mg + 4 * r][k] * wv;
    }
#pragma unroll
    for (int r = 0; r < MR; r++)
        part[((size_t)ks * 64 + mg + 4 * r) * N + n] = acc[r];
}

__global__ void skinny_reduce(const float* __restrict__ part, const float* __restrict__ bias,
                              float* __restrict__ C, int M, int N)
{
    int i = blockIdx.x * 256 + threadIdx.x;
    if (i < M * N) {
        int n = i & (N - 1);
        int m = i / N;
        float s = bias[n];
#pragma unroll
        for (int z = 0; z < 8; z++) s += part[((size_t)z * 64 + m) * N + n];
        C[i] = s;
    }
}

__global__ void skinny_reduce_addsq(const float* __restrict__ part, const float* __restrict__ bias,
                                    const float* __restrict__ sq, float* __restrict__ C)
{
    int i = blockIdx.x * 256 + threadIdx.x;
    int n = i & (DD - 1);
    int m = i / DD;
    float s = bias[n] + sq[i % (NS * DD)];
#pragma unroll
    for (int z = 0; z < 8; z++) s += part[((size_t)z * 64 + m) * DD + n];
    C[i] = s;
}

// ======================= dispatch attention =======================
__global__ void disp_scores(const float* __restrict__ qh, const float* __restrict__ kh,
                            float* __restrict__ sc)
{
    __shared__ float q[16][64];
    __shared__ float kt[128][65];
    const int j0 = blockIdx.x * 128;
    const int h  = blockIdx.y;
    const int b  = blockIdx.z;
    const int tid = threadIdx.x;

    for (int i = tid; i < NS * DH; i += 256) {
        int s = i >> 6, d = i & 63;
        q[s][d] = qh[(size_t)s * DD + h * DH + d];
    }
#pragma unroll
    for (int p = 0; p < 8; p++) {
        int idx = tid + p * 256;
        int jj = idx >> 4, d4 = (idx & 15) * 4;
        float4 v = *(const float4*)&kh[((size_t)b * LL + j0 + jj) * DD + h * DH + d4];
        kt[jj][d4 + 0] = v.x; kt[jj][d4 + 1] = v.y;
        kt[jj][d4 + 2] = v.z; kt[jj][d4 + 3] = v.w;
    }
    __syncthreads();

#pragma unroll
    for (int p = 0; p < 8; p++) {
        int idx = tid + p * 256;
        int s = idx >> 7, jj = idx & 127;
        float dot = 0.f;
#pragma unroll
        for (int d = 0; d < DH; d++) dot += q[s][d] * kt[jj][d];
        sc[(((size_t)b * HH + h) * NS + s) * LL + j0 + jj] = dot * 0.125f;
    }
}

__global__ void disp_softmax(float* __restrict__ sc)
{
    __shared__ float red[9];
    const int tid = threadIdx.x;
    float* r = sc + (size_t)blockIdx.x * LL;
    float v[8];
    float mx = -1e30f;
#pragma unroll
    for (int i = 0; i < 8; i++) { v[i] = r[tid + i * 256]; mx = fmaxf(mx, v[i]); }
#pragma unroll
    for (int o = 16; o; o >>= 1) mx = fmaxf(mx, __shfl_xor_sync(0xffffffffu, mx, o));
    int wd = tid >> 5, ln = tid & 31;
    if (!ln) red[wd] = mx;
    __syncthreads();
    if (tid < 32) {
        mx = (ln < 8) ? red[ln] : -1e30f;
#pragma unroll
        for (int o = 4; o; o >>= 1) mx = fmaxf(mx, __shfl_xor_sync(0xffffffffu, mx, o));
        if (!ln) red[8] = mx;
    }
    __syncthreads();
    mx = red[8];
    float sum = 0.f;
#pragma unroll
    for (int i = 0; i < 8; i++) { v[i] = __expf(v[i] - mx); sum += v[i]; }
#pragma unroll
    for (int o = 16; o; o >>= 1) sum += __shfl_xor_sync(0xffffffffu, sum, o);
    __syncthreads();
    if (!ln) red[wd] = sum;
    __syncthreads();
    if (tid < 32) {
        sum = (ln < 8) ? red[ln] : 0.f;
#pragma unroll
        for (int o = 4; o; o >>= 1) sum += __shfl_xor_sync(0xffffffffu, sum, o);
        if (!ln) red[8] = sum;
    }
    __syncthreads();
    float inv = 1.f / red[8];
#pragma unroll
    for (int i = 0; i < 8; i++) r[tid + i * 256] = v[i] * inv;
}

__global__ void disp_av(const float* __restrict__ sc, const float* __restrict__ vh,
                        float* __restrict__ part)
{
    __shared__ float p[16][132];
    __shared__ float vt[128][65];
    const int h = blockIdx.x, b = blockIdx.y, jz = blockIdx.z;
    const int j0 = jz * 128;
    const int tid = threadIdx.x;

#pragma unroll
    for (int q = 0; q < 2; q++) {
        int idx = tid + q * 256;
        int s = idx >> 5, j4 = (idx & 31) * 4;
        float4 v = *(const float4*)&sc[(((size_t)b * HH + h) * NS + s) * LL + j0 + j4];
        *(float4*)&p[s][j4] = v;
    }
#pragma unroll
    for (int q = 0; q < 8; q++) {
        int idx = tid + q * 256;
        int jj = idx >> 4, d4 = (idx & 15) * 4;
        float4 v = *(const float4*)&vh[((size_t)b * LL + j0 + jj) * DD + h * DH + d4];
        vt[jj][d4 + 0] = v.x; vt[jj][d4 + 1] = v.y;
        vt[jj][d4 + 2] = v.z; vt[jj][d4 + 3] = v.w;
    }
    __syncthreads();

    float acc[4] = {0.f, 0.f, 0.f, 0.f};
#pragma unroll 4
    for (int jj = 0; jj < 128; jj++) {
#pragma unroll
        for (int k = 0; k < 4; k++) {
            int idx = tid + k * 256;
            int s = idx >> 6, d = idx & 63;
            acc[k] += p[s][jj] * vt[jj][d];
        }
    }
#pragma unroll
    for (int k = 0; k < 4; k++) {
        int idx = tid + k * 256;
        int s = idx >> 6, d = idx & 63;
        part[(size_t)jz * (BB * NS * DD) + ((size_t)b * NS + s) * DD + h * DH + d] = acc[k];
    }
}

__global__ void disp_reduce(const float* __restrict__ part, float* __restrict__ att1)
{
    int i = blockIdx.x * 256 + threadIdx.x;
    float s = 0.f;
#pragma unroll
    for (int z = 0; z < 16; z++) s += part[(size_t)z * (BB * NS * DD) + i];
    att1[i] = s;
}

// ---------------- layernorm ----------------
__global__ void ln_kernel(const float* __restrict__ inp, const float* __restrict__ gam,
                          const float* __restrict__ bet, float* __restrict__ outp)
{
    const int row = blockIdx.x;
    const int e = row & (NS - 1);
    const float* xr = inp + (size_t)row * DD;
    __shared__ float r1[8], r2[8];
    float s1 = 0.f, s2 = 0.f;
    for (int d = threadIdx.x; d < DD; d += 256) {
        float v = xr[d];
        s1 += v; s2 += v * v;
    }
#pragma unroll
    for (int o = 16; o; o >>= 1) {
        s1 += __shfl_xor_sync(0xffffffffu, s1, o);
        s2 += __shfl_xor_sync(0xffffffffu, s2, o);
    }
    int wid = threadIdx.x >> 5, lane = threadIdx.x & 31;
    if (!lane) { r1[wid] = s1; r2[wid] = s2; }
    __syncthreads();
    if (threadIdx.x < 32) {
        s1 = (lane < 8) ? r1[lane] : 0.f;
        s2 = (lane < 8) ? r2[lane] : 0.f;
#pragma unroll
        for (int o = 4; o; o >>= 1) {
            s1 += __shfl_xor_sync(0xffffffffu, s1, o);
            s2 += __shfl_xor_sync(0xffffffffu, s2, o);
        }
        if (!lane) { r1[0] = s1; r2[0] = s2; }
    }
    __syncthreads();
    float mu  = r1[0] * (1.f / DD);
    float var = r2[0] * (1.f / DD) - mu * mu;
    float inv = rsqrtf(var + 1e-5f);
    for (int d = threadIdx.x; d < DD; d += 256)
        outp[(size_t)row * DD + d] = (xr[d] - mu) * inv * gam[(size_t)e * DD + d] + bet[(size_t)e * DD + d];
}

__device__ __forceinline__ float silu_f(float x) { return x / (1.f + __expf(-x)); }

// ---------------- expert up/gate: scalar-f streaming, full-chip ----------------
// grid (FF/128, EE) = (32,16) = 512 blocks, 128 threads; one f per thread
__global__ void expert_ug(const float* __restrict__ hn,
                          const float* __restrict__ W1, const float* __restrict__ b1,
                          const float* __restrict__ Wg, const float* __restrict__ bg,
                          float* __restrict__ ug)
{
    const int e = blockIdx.y;
    const int f = blockIdx.x * 128 + threadIdx.x;
    __shared__ float hs[BB][DD];
    for (int i = threadIdx.x; i < BB * DD / 4; i += 128) {
        int b = (i * 4) >> 10, d4 = (i * 4) & 1023;
        *(float4*)&hs[b][d4] = *(const float4*)&hn[((size_t)b * NS + e) * DD + d4];
    }
    __syncthreads();

    const float* w1 = W1 + (size_t)e * DD * FF + f;
    const float* wg = Wg + (size_t)e * DD * FF + f;
    float au[BB] = {0.f, 0.f, 0.f, 0.f};
    float ag[BB] = {0.f, 0.f, 0.f, 0.f};
#pragma unroll 8
    for (int d = 0; d < DD; d++) {
        float w1v = ldcs(&w1[(size_t)d * FF]);
        float wgv = ldcs(&wg[(size_t)d * FF]);
#pragma unroll
        for (int b = 0; b < BB; b++) {
            float hv = hs[b][d];
            au[b] += hv * w1v;
            ag[b] += hv * wgv;
        }
    }
    float bu = b1[(size_t)e * FF + f];
    float bv = bg[(size_t)e * FF + f];
#pragma unroll
    for (int b = 0; b < BB; b++)
        ug[((size_t)b * EE + e) * FF + f] = silu_f(au[b] + bu) * silu_f(ag[b] + bv);
}

// ---------------- expert down: scalar-d streaming, split-F 8 ----------------
// grid (DD/128, EE, 8) = (8,16,8) = 1024 blocks, 128 threads
__global__ void expert_w2p(const float* __restrict__ ug, const float* __restrict__ W2,
                           float* __restrict__ part)
{
    __shared__ float us[BB][512];
    const int e = blockIdx.y, fz = blockIdx.z;
    const int d = blockIdx.x * 128 + threadIdx.x;
    for (int i = threadIdx.x; i < BB * 512 / 4; i += 128) {
        int b = (i * 4) >> 9, f4 = (i * 4) & 511;
        *(float4*)&us[b][f4] = *(const float4*)&ug[((size_t)b * EE + e) * FF + fz * 512 + f4];
    }
    __syncthreads();
    const float* w = W2 + ((size_t)e * FF + fz * 512) * DD + d;
    float acc[BB] = {0.f, 0.f, 0.f, 0.f};
#pragma unroll 8
    for (int f = 0; f < 512; f++) {
        float wv = ldcs(&w[(size_t)f * DD]);
#pragma unroll
        for (int b = 0; b < BB; b++) acc[b] += us[b][f] * wv;
    }
#pragma unroll
    for (int b = 0; b < BB; b++)
        part[(size_t)fz * (BB * EE * DD) + ((size_t)b * EE + e) * DD + d] = acc[b];
}

__global__ void w2_reduce(const float* __restrict__ part, const float* __restrict__ b2,
                          float* __restrict__ o)
{
    int i = blockIdx.x * 256 + threadIdx.x;
    int d = i & 1023;
    int e = (i >> 10) & 15;
    float s = b2[(size_t)e * DD + d];
#pragma unroll
    for (int z = 0; z < 8; z++) s += part[(size_t)z * (BB * EE * DD) + i];
    o[i] += s;
}

// ---------------- combine attention ----------------
__global__ void combine_attn(const float* __restrict__ qh, const float* __restrict__ kh,
                             const float* __restrict__ vh, float* __restrict__ out)
{
    extern __shared__ float sm[];
    const int PITCH = HH * 65;
    float* qsm = sm;
    float* ksm = sm + 16 * PITCH;
    float* vsm = sm + 32 * PITCH;
    const int b  = blockIdx.y;
    const int t0 = blockIdx.x * 16;
    const int tid = threadIdx.x;

    for (int i = tid; i < NS * DD; i += 256) {
        int r = i >> 10, hd = i & 1023;
        int h = hd >> 6, d = hd & 63;
        int sw = r * PITCH + h * 65 + d;
        ksm[sw] = kh[(size_t)b * NS * DD + i];
        vsm[sw] = vh[(size_t)b * NS * DD + i];
        qsm[sw] = qh[((size_t)b * LL + t0) * DD + i];
    }
    __syncthreads();

    const int tt = tid >> 4;
    const int h  = tid & 15;

    float qreg[DH];
#pragma unroll
    for (int d = 0; d < DH; d++) qreg[d] = qsm[tt * PITCH + h * 65 + d];

    float sco[NS];
    float mx = -1e30f;
#pragma unroll
    for (int s = 0; s < NS; s++) {
        const float* kp = &ksm[s * PITCH + h * 65];
        float dot = 0.f;
#pragma unroll
        for (int d = 0; d < DH; d++) dot += qreg[d] * kp[d];
        dot *= 0.125f;
        sco[s] = dot;
        mx = fmaxf(mx, dot);
    }
    float sum = 0.f;
#pragma unroll
    for (int s = 0; s < NS; s++) { sco[s] = __expf(sco[s] - mx); sum += sco[s]; }
    float inv = 1.f / sum;

    float ov[DH];
#pragma unroll
    for (int d = 0; d < DH; d++) ov[d] = 0.f;
#pragma unroll
    for (int s = 0; s < NS; s++) {
        float pr = sco[s] * inv;
        const float* vp = &vsm[s * PITCH + h * 65];
#pragma unroll
        for (int d = 0; d < DH; d++) ov[d] += pr * vp[d];
    }
    __syncthreads();
#pragma unroll
    for (int d = 0; d < DH; d++) qsm[tt * PITCH + h * 65 + d] = ov[d];
    __syncthreads();
    for (int i = tid; i < NS * DD; i += 256) {
        int r = i >> 10, hd = i & 1023;
        int hh = hd >> 6, d = hd & 63;
        out[((size_t)b * LL + t0) * DD + i] = qsm[r * PITCH + hh * 65 + d];
    }
}

// ---------------- host launch ----------------
extern "C" void kernel_launch(void* const* d_in, const int* in_sizes, int n_in,
                              void* d_out, int out_size)
{
    const float* x    = (const float*)d_in[0];
    const float* sq   = (const float*)d_in[1];
    const float* dWq  = (const float*)d_in[2];
    const float* dWk  = (const float*)d_in[3];
    const float* dWv  = (const float*)d_in[4];
    const float* dWo  = (const float*)d_in[5];
    const float* dbq  = (const float*)d_in[6];
    const float* dbk  = (const float*)d_in[7];
    const float* dbv  = (const float*)d_in[8];
    const float* dbo  = (const float*)d_in[9];
    const float* cWq  = (const float*)d_in[10];
    const float* cWk  = (const float*)d_in[11];
    const float* cWv  = (const float*)d_in[12];
    const float* cWo  = (const float*)d_in[13];
    const float* cbq  = (const float*)d_in[14];
    const float* cbk  = (const float*)d_in[15];
    const float* cbv  = (const float*)d_in[16];
    const float* cbo  = (const float*)d_in[17];
    const float* elng = (const float*)d_in[18];
    const float* elnb = (const float*)d_in[19];
    const float* eW1  = (const float*)d_in[20];
    const float* eb1  = (const float*)d_in[21];
    const float* eWg  = (const float*)d_in[22];
    const float* ebg  = (const float*)d_in[23];
    const float* eW2  = (const float*)d_in[24];
    const float* eb2  = (const float*)d_in[25];
    float* out = (float*)d_out;

    float *kh, *vh, *qh1, *att1, *o, *hn, *ug, *qh2, *kh2, *vh2, *att2;
    float *sc, *avp, *skp, *w2p, *xtf, *wtf;
    cudaGetSymbolAddress((void**)&kh,   g_kh);
    cudaGetSymbolAddress((void**)&vh,   g_vh);
    cudaGetSymbolAddress((void**)&qh1,  g_qh1);
    cudaGetSymbolAddress((void**)&att1, g_att1);
    cudaGetSymbolAddress((void**)&o,    g_o);
    cudaGetSymbolAddress((void**)&hn,   g_hn);
    cudaGetSymbolAddress((void**)&ug,   g_ug);
    cudaGetSymbolAddress((void**)&qh2,  g_qh2);
    cudaGetSymbolAddress((void**)&kh2,  g_kh2);
    cudaGetSymbolAddress((void**)&vh2,  g_vh2);
    cudaGetSymbolAddress((void**)&att2, g_att2);
    cudaGetSymbolAddress((void**)&sc,   g_sc);
    cudaGetSymbolAddress((void**)&avp,  g_part);
    cudaGetSymbolAddress((void**)&skp,  g_skp);
    cudaGetSymbolAddress((void**)&w2p,  g_w2p);
    cudaGetSymbolAddress((void**)&xtf,  g_xtf);
    cudaGetSymbolAddress((void**)&wtf,  g_wtf);

    const int SMEM_COMB = 3 * 16 * (HH * 65) * 4;
    cudaFuncSetAttribute(combine_attn, cudaFuncAttributeMaxDynamicSharedMemorySize, SMEM_COMB);
    cudaFuncSetAttribute(gemm_tf32, cudaFuncAttributeMaxDynamicSharedMemorySize, GEMM_SMEM);

    dim3 gBig(DD / 128, (BB * LL) / 128);
    dim3 gSk(DD / 64, 8);
    const int W4 = DD * DD / 4;   // float4s per weight matrix

    // pre-round to tf32 (launch 4 = first big gemm -> profiled)
    cvt_tf32<<<W4 / 256, 256>>>(dWk, wtf + 0 * DD * DD, W4);                     // 1
    cvt_tf32<<<W4 / 256, 256>>>(dWv, wtf + 1 * DD * DD, W4);                     // 2
    cvt_tf32<<<(BB * LL * DD / 4) / 256, 256>>>(x, xtf, BB * LL * DD / 4);       // 3
    gemm_tf32<<<gBig, 256, GEMM_SMEM>>>(xtf, wtf + 0 * DD * DD, dbk, kh, BB * LL, DD, DD);  // 4 <- profiled
    gemm_tf32<<<gBig, 256, GEMM_SMEM>>>(xtf, wtf + 1 * DD * DD, dbv, vh, BB * LL, DD, DD);
    cvt_tf32<<<W4 / 256, 256>>>(cWq, wtf + 2 * DD * DD, W4);
    gemm_tf32<<<gBig, 256, GEMM_SMEM>>>(xtf, wtf + 2 * DD * DD, cbq, qh2, BB * LL, DD, DD);
    cvt_tf32<<<W4 / 256, 256>>>(cWo, wtf + 3 * DD * DD, W4);

    // dispatch Q projection
    gemm_skinny<16><<<gSk, 256>>>(sq, dWq, skp, DD, DD);
    skinny_reduce<<<(16 * DD) / 256, 256>>>(skp, dbq, qh1, 16, DD);

    // dispatch attention
    disp_scores<<<dim3(LL / 128, HH, BB), 256>>>(qh1, kh, sc);
    disp_softmax<<<BB * HH * NS, 256>>>(sc);
    disp_av<<<dim3(HH, BB, 16), 256>>>(sc, vh, avp);
    disp_reduce<<<(BB * NS * DD) / 256, 256>>>(avp, att1);

    // dispatch output projection + residual (fused)
    gemm_skinny<64><<<gSk, 256>>>(att1, dWo, skp, DD, DD);
    skinny_reduce_addsq<<<(64 * DD) / 256, 256>>>(skp, dbo, sq, o);

    // experts
    ln_kernel<<<BB * NS, 256>>>(o, elng, elnb, hn);
    expert_ug<<<dim3(FF / 128, EE), 128>>>(hn, eW1, eb1, eWg, ebg, ug);
    expert_w2p<<<dim3(DD / 128, EE, 8), 128>>>(ug, eW2, w2p);
    w2_reduce<<<(BB * EE * DD) / 256, 256>>>(w2p, eb2, o);

    // combine projections
    gemm_skinny<64><<<gSk, 256>>>(o, cWk, skp, DD, DD);
    skinny_reduce<<<(64 * DD) / 256, 256>>>(skp, cbk, kh2, 64, DD);
    gemm_skinny<64><<<gSk, 256>>>(o, cWv, skp, DD, DD);
    skinny_reduce<<<(64 * DD) / 256, 256>>>(skp, cbv, vh2, 64, DD);

    // combine attention + round + final projection
    combine_attn<<<dim3(LL / 16, BB), 256, SMEM_COMB>>>(qh2, kh2, vh2, att2);
    cvt_tf32<<<(BB * LL * DD / 4) / 256, 256>>>(att2, att2, BB * LL * DD / 4);
    gemm_tf32<<<gBig, 256, GEMM_SMEM>>>(att2, wtf + 3 * DD * DD, cbo, out, BB * LL, DD, DD);
}

// round 5
// speedup vs baseline: 1.3651x; 1.1020x over previous
#include <cuda_runtime.h>
#include <cuda_bf16.h>
#include <math.h>

#define BB 4
#define LL 2048
#define DD 1024
#define HH 16
#define DH 64
#define NS 16
#define EE 16
#define FF 4096

// ---------------- scratch ----------------
__device__ float g_kh  [BB*LL*DD];
__device__ float g_vh  [BB*LL*DD];
__device__ float g_qh1 [NS*DD];
__device__ float g_att1[BB*NS*DD];
__device__ float g_o   [BB*NS*DD];
__device__ float g_hn  [BB*NS*DD];
__device__ float g_ug  [BB*EE*FF];
__device__ float g_qh2 [BB*LL*DD];
__device__ float g_kh2 [BB*NS*DD];
__device__ float g_vh2 [BB*NS*DD];
__device__ float g_att2[BB*LL*DD];
__device__ float g_sc  [BB*HH*NS*LL];
__device__ float g_part[16*BB*NS*DD];
__device__ float g_skp [8*64*DD];
__device__ float g_w2p [8*BB*EE*DD];
__device__ float g_xtf [BB*LL*DD];
__device__ float g_wtf [4*DD*DD];

__device__ __forceinline__ float f2tf32f(float x) {
    unsigned y;
    asm("cvt.rna.tf32.f32 %0, %1;" : "=r"(y) : "f"(x));
    return __uint_as_float(y);
}

__device__ __forceinline__ void cpa16(float* dst, const float* src) {
    unsigned d = (unsigned)__cvta_generic_to_shared(dst);
    asm volatile("cp.async.cg.shared.global [%0], [%1], 16;\n" :: "r"(d), "l"(src));
}
__device__ __forceinline__ void cpa_commit() {
    asm volatile("cp.async.commit_group;\n" ::: "memory");
}
__device__ __forceinline__ void cpa_wait1() {
    asm volatile("cp.async.wait_group 1;\n" ::: "memory");
}

__device__ __forceinline__ float ldcs(const float* p) {
    float v;
    asm volatile("ld.global.cs.f32 %0, [%1];" : "=f"(v) : "l"(p));
    return v;
}

// ---------------- tf32 rounding pre-pass ----------------
__global__ void cvt_tf32(const float* __restrict__ src, float* __restrict__ dst, int n4)
{
    int i = blockIdx.x * 256 + threadIdx.x;
    if (i < n4) {
        float4 v = *(const float4*)&src[i * 4];
        v.x = f2tf32f(v.x); v.y = f2tf32f(v.y);
        v.z = f2tf32f(v.z); v.w = f2tf32f(v.w);
        *(float4*)&dst[i * 4] = v;
    }
}

// ======================= pipelined TF32 tensor-core GEMM =======================
#define APITCH 36
#define BPITCH 136
#define ASTG (128*APITCH)
#define BSTG (32*BPITCH)

__global__ __launch_bounds__(256)
void gemm_tf32(const float* __restrict__ A, const float* __restrict__ W,
               const float* __restrict__ bias, float* __restrict__ C,
               int M, int N, int K)
{
    extern __shared__ float smp[];
    float* As = smp;
    float* Bs = smp + 3 * ASTG;

    const int tid  = threadIdx.x;
    const int wid  = tid >> 5;
    const int lane = tid & 31;
    const int g    = lane >> 2;
    const int tig  = lane & 3;
    const int wm0  = (wid >> 2) * 64;
    const int wn0  = (wid & 3) * 32;
    const int row0 = blockIdx.y * 128;
    const int col0 = blockIdx.x * 128;

    const int am = tid >> 3;
    const int ak = (tid & 7) * 4;
    const int bk = tid >> 5;
    const int bn = (tid & 31) * 4;

    const int NT = K >> 5;

    auto load_stage = [&](int tile, int st) {
        const int k0 = tile * 32;
        float* as = As + st * ASTG;
        float* bs = Bs + st * BSTG;
#pragma unroll
        for (int p = 0; p < 4; p++) {
            int m = am + p * 32;
            cpa16(&as[m * APITCH + ak], &A[(size_t)(row0 + m) * K + k0 + ak]);
            int kb = bk + p * 8;
            cpa16(&bs[kb * BPITCH + bn], &W[(size_t)(k0 + kb) * N + col0 + bn]);
        }
    };

    float acc[4][4][4];
#pragma unroll
    for (int i = 0; i < 4; i++)
#pragma unroll
        for (int j = 0; j < 4; j++)
#pragma unroll
            for (int c = 0; c < 4; c++) acc[i][j][c] = 0.f;

    load_stage(0, 0); cpa_commit();
    load_stage(1, 1); cpa_commit();

    int st = 0;
    for (int i = 0; i < NT; i++) {
        cpa_wait1();
        __syncthreads();

        const float* asf = As + st * ASTG;
        const float* bsf = Bs + st * BSTG;
#pragma unroll
        for (int kk = 0; kk < 4; kk++) {
            unsigned af[4][4];
#pragma unroll
            for (int mt = 0; mt < 4; mt++) {
                int mb = wm0 + mt * 16;
                af[mt][0] = __float_as_uint(asf[(mb + g    ) * APITCH + kk * 8 + tig]);
                af[mt][1] = __float_as_uint(asf[(mb + 8 + g) * APITCH + kk * 8 + tig]);
                af[mt][2] = __float_as_uint(asf[(mb + g    ) * APITCH + kk * 8 + tig + 4]);
                af[mt][3] = __float_as_uint(asf[(mb + 8 + g) * APITCH + kk * 8 + tig + 4]);
            }
            unsigned bf[4][2];
#pragma unroll
            for (int nt = 0; nt < 4; nt++) {
                bf[nt][0] = __float_as_uint(bsf[(kk * 8 + tig    ) * BPITCH + wn0 + nt * 8 + g]);
                bf[nt][1] = __float_as_uint(bsf[(kk * 8 + tig + 4) * BPITCH + wn0 + nt * 8 + g]);
            }
#pragma unroll
            for (int mt = 0; mt < 4; mt++)
#pragma unroll
                for (int nt = 0; nt < 4; nt++) {
                    asm volatile(
                        "mma.sync.aligned.m16n8k8.row.col.f32.tf32.tf32.f32 "
                        "{%0,%1,%2,%3}, {%4,%5,%6,%7}, {%8,%9}, {%0,%1,%2,%3};\n"
                        : "+f"(acc[mt][nt][0]), "+f"(acc[mt][nt][1]),
                          "+f"(acc[mt][nt][2]), "+f"(acc[mt][nt][3])
                        : "r"(af[mt][0]), "r"(af[mt][1]), "r"(af[mt][2]), "r"(af[mt][3]),
                          "r"(bf[nt][0]), "r"(bf[nt][1]));
                }
        }

        if (i + 2 < NT) { load_stage(i + 2, (st + 2) % 3); }
        cpa_commit();
        st = (st + 1) % 3;
    }

#pragma unroll
    for (int mt = 0; mt < 4; mt++) {
#pragma unroll
        for (int nt = 0; nt < 4; nt++) {
            int r = row0 + wm0 + mt * 16 + g;
            int c = col0 + wn0 + nt * 8 + tig * 2;
            float b0v = bias[c], b1v = bias[c + 1];
            float2 v0 = make_float2(acc[mt][nt][0] + b0v, acc[mt][nt][1] + b1v);
            float2 v1 = make_float2(acc[mt][nt][2] + b0v, acc[mt][nt][3] + b1v);
            *(float2*)&C[(size_t)r * N + c] = v0;
            *(float2*)&C[(size_t)(r + 8) * N + c] = v1;
        }
    }
}
#define GEMM_SMEM (3 * (ASTG + BSTG) * 4)

// ======================= skinny split-K GEMM (M<=64) =======================
template<int M>
__global__ void gemm_skinny(const float* __restrict__ A, const float* __restrict__ W,
                            float* __restrict__ part, int N, int K)
{
    __shared__ float As[64][132];
    const int tid = threadIdx.x;
    const int ks = blockIdx.y;
    const int n  = blockIdx.x * 64 + (tid & 63);
    const int mg = tid >> 6;
    const int k0 = ks * 128;

    for (int idx = tid; idx < M * 32; idx += 256) {
        int m = idx >> 5, c4 = (idx & 31) * 4;
        *(float4*)&As[m][c4] = *(const float4*)&A[(size_t)m * K + k0 + c4];
    }
    __syncthreads();

    const int MR = M / 4;
    float acc[MR];
#pragma unroll
    for (int r = 0; r < MR; r++) acc[r] = 0.f;

#pragma unroll 4
    for (int k = 0; k < 128; k++) {
        float wv = __ldg(&W[(size_t)(k0 + k) * N + n]);
#pragma unroll
        for (int r = 0; r < MR; r++) acc[r] += As[mg + 4 * r][k] * wv;
    }
#pragma unroll
    for (int r = 0; r < MR; r++)
        part[((size_t)ks * 64 + mg + 4 * r) * N + n] = acc[r];
}

__global__ void skinny_reduce(const float* __restrict__ part, const float* __restrict__ bias,
                              float* __restrict__ C, int M, int N)
{
    int i = blockIdx.x * 256 + threadIdx.x;
    if (i < M * N) {
        int n = i & (N - 1);
        int m = i / N;
        float s = bias[n];
#pragma unroll
        for (int z = 0; z < 8; z++) s += part[((size_t)z * 64 + m) * N + n];
        C[i] = s;
    }
}

__global__ void skinny_reduce_addsq(const float* __restrict__ part, const float* __restrict__ bias,
                                    const float* __restrict__ sq, float* __restrict__ C)
{
    int i = blockIdx.x * 256 + threadIdx.x;
    int n = i & (DD - 1);
    int m = i / DD;
    float s = bias[n] + sq[i % (NS * DD)];
#pragma unroll
    for (int z = 0; z < 8; z++) s += part[((size_t)z * 64 + m) * DD + n];
    C[i] = s;
}

// ======================= dispatch attention =======================
__global__ void disp_scores(const float* __restrict__ qh, const float* __restrict__ kh,
                            float* __restrict__ sc)
{
    __shared__ float q[16][64];
    __shared__ float kt[128][65];
    const int j0 = blockIdx.x * 128;
    const int h  = blockIdx.y;
    const int b  = blockIdx.z;
    const int tid = threadIdx.x;

    for (int i = tid; i < NS * DH; i += 256) {
        int s = i >> 6, d = i & 63;
        q[s][d] = qh[(size_t)s * DD + h * DH + d];
    }
#pragma unroll
    for (int p = 0; p < 8; p++) {
        int idx = tid + p * 256;
        int jj = idx >> 4, d4 = (idx & 15) * 4;
        float4 v = *(const float4*)&kh[((size_t)b * LL + j0 + jj) * DD + h * DH + d4];
        kt[jj][d4 + 0] = v.x; kt[jj][d4 + 1] = v.y;
        kt[jj][d4 + 2] = v.z; kt[jj][d4 + 3] = v.w;
    }
    __syncthreads();

#pragma unroll
    for (int p = 0; p < 8; p++) {
        int idx = tid + p * 256;
        int s = idx >> 7, jj = idx & 127;
        float dot = 0.f;
#pragma unroll
        for (int d = 0; d < DH; d++) dot += q[s][d] * kt[jj][d];
        sc[(((size_t)b * HH + h) * NS + s) * LL + j0 + jj] = dot * 0.125f;
    }
}

__global__ void disp_softmax(float* __restrict__ sc)
{
    __shared__ float red[9];
    const int tid = threadIdx.x;
    float* r = sc + (size_t)blockIdx.x * LL;
    float v[8];
    float mx = -1e30f;
#pragma unroll
    for (int i = 0; i < 8; i++) { v[i] = r[tid + i * 256]; mx = fmaxf(mx, v[i]); }
#pragma unroll
    for (int o = 16; o; o >>= 1) mx = fmaxf(mx, __shfl_xor_sync(0xffffffffu, mx, o));
    int wd = tid >> 5, ln = tid & 31;
    if (!ln) red[wd] = mx;
    __syncthreads();
    if (tid < 32) {
        mx = (ln < 8) ? red[ln] : -1e30f;
#pragma unroll
        for (int o = 4; o; o >>= 1) mx = fmaxf(mx, __shfl_xor_sync(0xffffffffu, mx, o));
        if (!ln) red[8] = mx;
    }
    __syncthreads();
    mx = red[8];
    float sum = 0.f;
#pragma unroll
    for (int i = 0; i < 8; i++) { v[i] = __expf(v[i] - mx); sum += v[i]; }
#pragma unroll
    for (int o = 16; o; o >>= 1) sum += __shfl_xor_sync(0xffffffffu, sum, o);
    __syncthreads();
    if (!ln) red[wd] = sum;
    __syncthreads();
    if (tid < 32) {
        sum = (ln < 8) ? red[ln] : 0.f;
#pragma unroll
        for (int o = 4; o; o >>= 1) sum += __shfl_xor_sync(0xffffffffu, sum, o);
        if (!ln) red[8] = sum;
    }
    __syncthreads();
    float inv = 1.f / red[8];
#pragma unroll
    for (int i = 0; i < 8; i++) r[tid + i * 256] = v[i] * inv;
}

__global__ void disp_av(const float* __restrict__ sc, const float* __restrict__ vh,
                        float* __restrict__ part)
{
    __shared__ float p[16][132];
    __shared__ float vt[128][65];
    const int h = blockIdx.x, b = blockIdx.y, jz = blockIdx.z;
    const int j0 = jz * 128;
    const int tid = threadIdx.x;

#pragma unroll
    for (int q = 0; q < 2; q++) {
        int idx = tid + q * 256;
        int s = idx >> 5, j4 = (idx & 31) * 4;
        float4 v = *(const float4*)&sc[(((size_t)b * HH + h) * NS + s) * LL + j0 + j4];
        *(float4*)&p[s][j4] = v;
    }
#pragma unroll
    for (int q = 0; q < 8; q++) {
        int idx = tid + q * 256;
        int jj = idx >> 4, d4 = (idx & 15) * 4;
        float4 v = *(const float4*)&vh[((size_t)b * LL + j0 + jj) * DD + h * DH + d4];
        vt[jj][d4 + 0] = v.x; vt[jj][d4 + 1] = v.y;
        vt[jj][d4 + 2] = v.z; vt[jj][d4 + 3] = v.w;
    }
    __syncthreads();

    float acc[4] = {0.f, 0.f, 0.f, 0.f};
#pragma unroll 4
    for (int jj = 0; jj < 128; jj++) {
#pragma unroll
        for (int k = 0; k < 4; k++) {
            int idx = tid + k * 256;
            int s = idx >> 6, d = idx & 63;
            acc[k] += p[s][jj] * vt[jj][d];
        }
    }
#pragma unroll
    for (int k = 0; k < 4; k++) {
        int idx = tid + k * 256;
        int s = idx >> 6, d = idx & 63;
        part[(size_t)jz * (BB * NS * DD) + ((size_t)b * NS + s) * DD + h * DH + d] = acc[k];
    }
}

__global__ void disp_reduce(const float* __restrict__ part, float* __restrict__ att1)
{
    int i = blockIdx.x * 256 + threadIdx.x;
    float s = 0.f;
#pragma unroll
    for (int z = 0; z < 16; z++) s += part[(size_t)z * (BB * NS * DD) + i];
    att1[i] = s;
}

// ---------------- layernorm ----------------
__global__ void ln_kernel(const float* __restrict__ inp, const float* __restrict__ gam,
                          const float* __restrict__ bet, float* __restrict__ outp)
{
    const int row = blockIdx.x;
    const int e = row & (NS - 1);
    const float* xr = inp + (size_t)row * DD;
    __shared__ float r1[8], r2[8];
    float s1 = 0.f, s2 = 0.f;
    for (int d = threadIdx.x; d < DD; d += 256) {
        float v = xr[d];
        s1 += v; s2 += v * v;
    }
#pragma unroll
    for (int o = 16; o; o >>= 1) {
        s1 += __shfl_xor_sync(0xffffffffu, s1, o);
        s2 += __shfl_xor_sync(0xffffffffu, s2, o);
    }
    int wid = threadIdx.x >> 5, lane = threadIdx.x & 31;
    if (!lane) { r1[wid] = s1; r2[wid] = s2; }
    __syncthreads();
    if (threadIdx.x < 32) {
        s1 = (lane < 8) ? r1[lane] : 0.f;
        s2 = (lane < 8) ? r2[lane] : 0.f;
#pragma unroll
        for (int o = 4; o; o >>= 1) {
            s1 += __shfl_xor_sync(0xffffffffu, s1, o);
            s2 += __shfl_xor_sync(0xffffffffu, s2, o);
        }
        if (!lane) { r1[0] = s1; r2[0] = s2; }
    }
    __syncthreads();
    float mu  = r1[0] * (1.f / DD);
    float var = r2[0] * (1.f / DD) - mu * mu;
    float inv = rsqrtf(var + 1e-5f);
    for (int d = threadIdx.x; d < DD; d += 256)
        outp[(size_t)row * DD + d] = (xr[d] - mu) * inv * gam[(size_t)e * DD + d] + bet[(size_t)e * DD + d];
}

__device__ __forceinline__ float silu_f(float x) { return x / (1.f + __expf(-x)); }

// ---------------- expert up/gate ----------------
__global__ void expert_ug(const float* __restrict__ hn,
                          const float* __restrict__ W1, const float* __restrict__ b1,
                          const float* __restrict__ Wg, const float* __restrict__ bg,
                          float* __restrict__ ug)
{
    const int e = blockIdx.y;
    const int f = blockIdx.x * 128 + threadIdx.x;
    __shared__ float hs[BB][DD];
    for (int i = threadIdx.x; i < BB * DD / 4; i += 128) {
        int b = (i * 4) >> 10, d4 = (i * 4) & 1023;
        *(float4*)&hs[b][d4] = *(const float4*)&hn[((size_t)b * NS + e) * DD + d4];
    }
    __syncthreads();

    const float* w1 = W1 + (size_t)e * DD * FF + f;
    const float* wg = Wg + (size_t)e * DD * FF + f;
    float au[BB] = {0.f, 0.f, 0.f, 0.f};
    float ag[BB] = {0.f, 0.f, 0.f, 0.f};
#pragma unroll 16
    for (int d = 0; d < DD; d++) {
        float w1v = ldcs(&w1[(size_t)d * FF]);
        float wgv = ldcs(&wg[(size_t)d * FF]);
#pragma unroll
        for (int b = 0; b < BB; b++) {
            float hv = hs[b][d];
            au[b] += hv * w1v;
            ag[b] += hv * wgv;
        }
    }
    float bu = b1[(size_t)e * FF + f];
    float bv = bg[(size_t)e * FF + f];
#pragma unroll
    for (int b = 0; b < BB; b++)
        ug[((size_t)b * EE + e) * FF + f] = silu_f(au[b] + bu) * silu_f(ag[b] + bv);
}

// ---------------- expert down: split-F partials ----------------
__global__ void expert_w2p(const float* __restrict__ ug, const float* __restrict__ W2,
                           float* __restrict__ part)
{
    __shared__ float us[BB][512];
    const int e = blockIdx.y, fz = blockIdx.z;
    const int d = blockIdx.x * 128 + threadIdx.x;
    for (int i = threadIdx.x; i < BB * 512 / 4; i += 128) {
        int b = (i * 4) >> 9, f4 = (i * 4) & 511;
        *(float4*)&us[b][f4] = *(const float4*)&ug[((size_t)b * EE + e) * FF + fz * 512 + f4];
    }
    __syncthreads();
    const float* w = W2 + ((size_t)e * FF + fz * 512) * DD + d;
    float acc[BB] = {0.f, 0.f, 0.f, 0.f};
#pragma unroll 16
    for (int f = 0; f < 512; f++) {
        float wv = ldcs(&w[(size_t)f * DD]);
#pragma unroll
        for (int b = 0; b < BB; b++) acc[b] += us[b][f] * wv;
    }
#pragma unroll
    for (int b = 0; b < BB; b++)
        part[(size_t)fz * (BB * EE * DD) + ((size_t)b * EE + e) * DD + d] = acc[b];
}

__global__ void w2_reduce(const float* __restrict__ part, const float* __restrict__ b2,
                          float* __restrict__ o)
{
    int i = blockIdx.x * 256 + threadIdx.x;
    int d = i & 1023;
    int e = (i >> 10) & 15;
    float s = b2[(size_t)e * DD + d];
#pragma unroll
    for (int z = 0; z < 8; z++) s += part[(size_t)z * (BB * EE * DD) + i];
    o[i] += s;
}

// ---------------- combine attention (output pre-rounded to tf32) ----------------
__global__ void combine_attn(const float* __restrict__ qh, const float* __restrict__ kh,
                             const float* __restrict__ vh, float* __restrict__ out)
{
    extern __shared__ float sm[];
    const int PITCH = HH * 65;
    float* qsm = sm;
    float* ksm = sm + 16 * PITCH;
    float* vsm = sm + 32 * PITCH;
    const int b  = blockIdx.y;
    const int t0 = blockIdx.x * 16;
    const int tid = threadIdx.x;

    for (int i = tid; i < NS * DD; i += 256) {
        int r = i >> 10, hd = i & 1023;
        int h = hd >> 6, d = hd & 63;
        int sw = r * PITCH + h * 65 + d;
        ksm[sw] = kh[(size_t)b * NS * DD + i];
        vsm[sw] = vh[(size_t)b * NS * DD + i];
        qsm[sw] = qh[((size_t)b * LL + t0) * DD + i];
    }
    __syncthreads();

    const int tt = tid >> 4;
    const int h  = tid & 15;

    float qreg[DH];
#pragma unroll
    for (int d = 0; d < DH; d++) qreg[d] = qsm[tt * PITCH + h * 65 + d];

    float sco[NS];
    float mx = -1e30f;
#pragma unroll
    for (int s = 0; s < NS; s++) {
        const float* kp = &ksm[s * PITCH + h * 65];
        float dot = 0.f;
#pragma unroll
        for (int d = 0; d < DH; d++) dot += qreg[d] * kp[d];
        dot *= 0.125f;
        sco[s] = dot;
        mx = fmaxf(mx, dot);
    }
    float sum = 0.f;
#pragma unroll
    for (int s = 0; s < NS; s++) { sco[s] = __expf(sco[s] - mx); sum += sco[s]; }
    float inv = 1.f / sum;

    float ov[DH];
#pragma unroll
    for (int d = 0; d < DH; d++) ov[d] = 0.f;
#pragma unroll
    for (int s = 0; s < NS; s++) {
        float pr = sco[s] * inv;
        const float* vp = &vsm[s * PITCH + h * 65];
#pragma unroll
        for (int d = 0; d < DH; d++) ov[d] += pr * vp[d];
    }
    __syncthreads();
#pragma unroll
    for (int d = 0; d < DH; d++) qsm[tt * PITCH + h * 65 + d] = ov[d];
    __syncthreads();
    // fused tf32 rounding on output (feeds the final tensor GEMM)
    for (int i = tid; i < NS * DD; i += 256) {
        int r = i >> 10, hd = i & 1023;
        int hh = hd >> 6, d = hd & 63;
        out[((size_t)b * LL + t0) * DD + i] = f2tf32f(qsm[r * PITCH + hh * 65 + d]);
    }
}

// ---------------- host launch ----------------
extern "C" void kernel_launch(void* const* d_in, const int* in_sizes, int n_in,
                              void* d_out, int out_size)
{
    const float* x    = (const float*)d_in[0];
    const float* sq   = (const float*)d_in[1];
    const float* dWq  = (const float*)d_in[2];
    const float* dWk  = (const float*)d_in[3];
    const float* dWv  = (const float*)d_in[4];
    const float* dWo  = (const float*)d_in[5];
    const float* dbq  = (const float*)d_in[6];
    const float* dbk  = (const float*)d_in[7];
    const float* dbv  = (const float*)d_in[8];
    const float* dbo  = (const float*)d_in[9];
    const float* cWq  = (const float*)d_in[10];
    const float* cWk  = (const float*)d_in[11];
    const float* cWv  = (const float*)d_in[12];
    const float* cWo  = (const float*)d_in[13];
    const float* cbq  = (const float*)d_in[14];
    const float* cbk  = (const float*)d_in[15];
    const float* cbv  = (const float*)d_in[16];
    const float* cbo  = (const float*)d_in[17];
    const float* elng = (const float*)d_in[18];
    const float* elnb = (const float*)d_in[19];
    const float* eW1  = (const float*)d_in[20];
    const float* eb1  = (const float*)d_in[21];
    const float* eWg  = (const float*)d_in[22];
    const float* ebg  = (const float*)d_in[23];
    const float* eW2  = (const float*)d_in[24];
    const float* eb2  = (const float*)d_in[25];
    float* out = (float*)d_out;

    float *kh, *vh, *qh1, *att1, *o, *hn, *ug, *qh2, *kh2, *vh2, *att2;
    float *sc, *avp, *skp, *w2p, *xtf, *wtf;
    cudaGetSymbolAddress((void**)&kh,   g_kh);
    cudaGetSymbolAddress((void**)&vh,   g_vh);
    cudaGetSymbolAddress((void**)&qh1,  g_qh1);
    cudaGetSymbolAddress((void**)&att1, g_att1);
    cudaGetSymbolAddress((void**)&o,    g_o);
    cudaGetSymbolAddress((void**)&hn,   g_hn);
    cudaGetSymbolAddress((void**)&ug,   g_ug);
    cudaGetSymbolAddress((void**)&qh2,  g_qh2);
    cudaGetSymbolAddress((void**)&kh2,  g_kh2);
    cudaGetSymbolAddress((void**)&vh2,  g_vh2);
    cudaGetSymbolAddress((void**)&att2, g_att2);
    cudaGetSymbolAddress((void**)&sc,   g_sc);
    cudaGetSymbolAddress((void**)&avp,  g_part);
    cudaGetSymbolAddress((void**)&skp,  g_skp);
    cudaGetSymbolAddress((void**)&w2p,  g_w2p);
    cudaGetSymbolAddress((void**)&xtf,  g_xtf);
    cudaGetSymbolAddress((void**)&wtf,  g_wtf);

    // streams/events (created once; no device memory involved)
    static cudaStream_t s1 = nullptr, s2 = nullptr, s3 = nullptr;
    static cudaEvent_t ev0, evx, evq, evvh, evs3;
    if (!s1) {
        cudaStreamCreateWithFlags(&s1, cudaStreamNonBlocking);
        cudaStreamCreateWithFlags(&s2, cudaStreamNonBlocking);
        cudaStreamCreateWithFlags(&s3, cudaStreamNonBlocking);
        cudaEventCreateWithFlags(&ev0,  cudaEventDisableTiming);
        cudaEventCreateWithFlags(&evx,  cudaEventDisableTiming);
        cudaEventCreateWithFlags(&evq,  cudaEventDisableTiming);
        cudaEventCreateWithFlags(&evvh, cudaEventDisableTiming);
        cudaEventCreateWithFlags(&evs3, cudaEventDisableTiming);
    }

    const int SMEM_COMB = 3 * 16 * (HH * 65) * 4;
    cudaFuncSetAttribute(combine_attn, cudaFuncAttributeMaxDynamicSharedMemorySize, SMEM_COMB);
    cudaFuncSetAttribute(gemm_tf32, cudaFuncAttributeMaxDynamicSharedMemorySize, GEMM_SMEM);

    dim3 gBig(DD / 128, (BB * LL) / 128);
    dim3 gSk(DD / 64, 8);
    const int W4 = DD * DD / 4;
    const int X4 = BB * LL * DD / 4;

    // ---- fork point ----
    cudaEventRecord(ev0, 0);

    // L: x rounding + dWk cvt + kh GEMM
    cvt_tf32<<<X4 / 256, 256>>>(x, xtf, X4);                                     // 1
    cudaEventRecord(evx, 0);
    cvt_tf32<<<W4 / 256, 256>>>(dWk, wtf + 0 * DD * DD, W4);                     // 2

    // s1: vh GEMM (needs xtf)
    cudaStreamWaitEvent(s1, evx, 0);
    cvt_tf32<<<W4 / 256, 256, 0, s1>>>(dWv, wtf + 1 * DD * DD, W4);              // 3

    gemm_tf32<<<gBig, 256, GEMM_SMEM>>>(xtf, wtf + 0 * DD * DD, dbk, kh, BB * LL, DD, DD);  // 4 <- profiled
    gemm_tf32<<<gBig, 256, GEMM_SMEM, s1>>>(xtf, wtf + 1 * DD * DD, dbv, vh, BB * LL, DD, DD);
    cudaEventRecord(evvh, s1);

    // s3: qh2 GEMM + cWo cvt (overlaps dispatch/expert phase)
    cudaStreamWaitEvent(s3, evx, 0);
    cvt_tf32<<<W4 / 256, 256, 0, s3>>>(cWq, wtf + 2 * DD * DD, W4);
    gemm_tf32<<<gBig, 256, GEMM_SMEM, s3>>>(xtf, wtf + 2 * DD * DD, cbq, qh2, BB * LL, DD, DD);
    cvt_tf32<<<W4 / 256, 256, 0, s3>>>(cWo, wtf + 3 * DD * DD, W4);
    cudaEventRecord(evs3, s3);

    // s2: dispatch Q projection (independent of x)
    cudaStreamWaitEvent(s2, ev0, 0);
    gemm_skinny<16><<<gSk, 256, 0, s2>>>(sq, dWq, skp, DD, DD);
    skinny_reduce<<<(16 * DD) / 256, 256, 0, s2>>>(skp, dbq, qh1, 16, DD);
    cudaEventRecord(evq, s2);

    // L: dispatch attention (needs kh [L], qh1 [s2], vh [s1])
    cudaStreamWaitEvent(0, evq, 0);
    disp_scores<<<dim3(LL / 128, HH, BB), 256>>>(qh1, kh, sc);
    disp_softmax<<<BB * HH * NS, 256>>>(sc);
    cudaStreamWaitEvent(0, evvh, 0);
    disp_av<<<dim3(HH, BB, 16), 256>>>(sc, vh, avp);
    disp_reduce<<<(BB * NS * DD) / 256, 256>>>(avp, att1);

    // dispatch output projection + residual
    gemm_skinny<64><<<gSk, 256>>>(att1, dWo, skp, DD, DD);
    skinny_reduce_addsq<<<(64 * DD) / 256, 256>>>(skp, dbo, sq, o);

    // experts
    ln_kernel<<<BB * NS, 256>>>(o, elng, elnb, hn);
    expert_ug<<<dim3(FF / 128, EE), 128>>>(hn, eW1, eb1, eWg, ebg, ug);
    expert_w2p<<<dim3(DD / 128, EE, 8), 128>>>(ug, eW2, w2p);
    w2_reduce<<<(BB * EE * DD) / 256, 256>>>(w2p, eb2, o);

    // combine projections
    gemm_skinny<64><<<gSk, 256>>>(o, cWk, skp, DD, DD);
    skinny_reduce<<<(64 * DD) / 256, 256>>>(skp, cbk, kh2, 64, DD);
    gemm_skinny<64><<<gSk, 256>>>(o, cWv, skp, DD, DD);
    skinny_reduce<<<(64 * DD) / 256, 256>>>(skp, cbv, vh2, 64, DD);

    // join s3 (qh2 + wtf3), then combine attention + final projection
    cudaStreamWaitEvent(0, evs3, 0);
    combine_attn<<<dim3(LL / 16, BB), 256, SMEM_COMB>>>(qh2, kh2, vh2, att2);
    gemm_tf32<<<gBig, 256, GEMM_SMEM>>>(att2, wtf + 3 * DD * DD, cbo, out, BB * LL, DD, DD);
}

// round 6
// speedup vs baseline: 1.4319x; 1.0489x over previous
#include <cuda_runtime.h>
#include <cuda_bf16.h>
#include <math.h>

#define BB 4
#define LL 2048
#define DD 1024
#define HH 16
#define DH 64
#define NS 16
#define EE 16
#define FF 4096

// ---------------- scratch ----------------
__device__ float g_kh  [BB*LL*DD];
__device__ float g_vh  [BB*LL*DD];
__device__ float g_qh1 [NS*DD];
__device__ float g_att1[BB*NS*DD];
__device__ float g_o   [BB*NS*DD];
__device__ float g_hn  [BB*NS*DD];
__device__ float g_ug  [BB*EE*FF];
__device__ float g_qh2 [BB*LL*DD];
__device__ float g_kh2 [BB*NS*DD];
__device__ float g_vh2 [BB*NS*DD];
__device__ float g_att2[BB*LL*DD];
__device__ float g_sc  [BB*HH*NS*LL];
__device__ float g_part[16*BB*NS*DD];
__device__ float g_skp [8*64*DD];
__device__ float g_w2p [8*BB*EE*DD];
__device__ float g_xtf [BB*LL*DD];
__device__ float g_wtf [4*DD*DD];

__device__ __forceinline__ float f2tf32f(float x) {
    unsigned y;
    asm("cvt.rna.tf32.f32 %0, %1;" : "=r"(y) : "f"(x));
    return __uint_as_float(y);
}

__device__ __forceinline__ void cpa16(float* dst, const float* src) {
    unsigned d = (unsigned)__cvta_generic_to_shared(dst);
    asm volatile("cp.async.cg.shared.global [%0], [%1], 16;\n" :: "r"(d), "l"(src));
}
__device__ __forceinline__ void cpa_commit() {
    asm volatile("cp.async.commit_group;\n" ::: "memory");
}
__device__ __forceinline__ void cpa_wait1() {
    asm volatile("cp.async.wait_group 1;\n" ::: "memory");
}

__device__ __forceinline__ float ldcs(const float* p) {
    float v;
    asm volatile("ld.global.cs.f32 %0, [%1];" : "=f"(v) : "l"(p));
    return v;
}

// ---------------- tf32 rounding pre-passes ----------------
__global__ void cvt_tf32(const float* __restrict__ src, float* __restrict__ dst, int n4)
{
    int i = blockIdx.x * 256 + threadIdx.x;
    if (i < n4) {
        float4 v = *(const float4*)&src[i * 4];
        v.x = f2tf32f(v.x); v.y = f2tf32f(v.y);
        v.z = f2tf32f(v.z); v.w = f2tf32f(v.w);
        *(float4*)&dst[i * 4] = v;
    }
}

// 4 weight matrices in one launch (blockIdx.y selects)
__global__ void cvt_w4(const float* __restrict__ s0, const float* __restrict__ s1,
                       const float* __restrict__ s2, const float* __restrict__ s3,
                       float* __restrict__ dst)
{
    int i = blockIdx.x * 256 + threadIdx.x;
    int y = blockIdx.y;
    const float* s = (y == 0) ? s0 : (y == 1) ? s1 : (y == 2) ? s2 : s3;
    float4 v = *(const float4*)&s[i * 4];
    v.x = f2tf32f(v.x); v.y = f2tf32f(v.y);
    v.z = f2tf32f(v.z); v.w = f2tf32f(v.w);
    *(float4*)&dst[(size_t)y * DD * DD + i * 4] = v;
}

// ======================= pipelined TF32 tensor-core GEMM =======================
#define APITCH 36
#define BPITCH 136
#define ASTG (128*APITCH)
#define BSTG (32*BPITCH)

__global__ __launch_bounds__(256)
void gemm_tf32(const float* __restrict__ A, const float* __restrict__ W,
               const float* __restrict__ bias, float* __restrict__ C,
               int M, int N, int K)
{
    extern __shared__ float smp[];
    float* As = smp;
    float* Bs = smp + 3 * ASTG;

    const int tid  = threadIdx.x;
    const int wid  = tid >> 5;
    const int lane = tid & 31;
    const int g    = lane >> 2;
    const int tig  = lane & 3;
    const int wm0  = (wid >> 2) * 64;
    const int wn0  = (wid & 3) * 32;
    const int row0 = blockIdx.y * 128;
    const int col0 = blockIdx.x * 128;

    const int am = tid >> 3;
    const int ak = (tid & 7) * 4;
    const int bk = tid >> 5;
    const int bn = (tid & 31) * 4;

    const int NT = K >> 5;

    auto load_stage = [&](int tile, int st) {
        const int k0 = tile * 32;
        float* as = As + st * ASTG;
        float* bs = Bs + st * BSTG;
#pragma unroll
        for (int p = 0; p < 4; p++) {
            int m = am + p * 32;
            cpa16(&as[m * APITCH + ak], &A[(size_t)(row0 + m) * K + k0 + ak]);
            int kb = bk + p * 8;
            cpa16(&bs[kb * BPITCH + bn], &W[(size_t)(k0 + kb) * N + col0 + bn]);
        }
    };

    float acc[4][4][4];
#pragma unroll
    for (int i = 0; i < 4; i++)
#pragma unroll
        for (int j = 0; j < 4; j++)
#pragma unroll
            for (int c = 0; c < 4; c++) acc[i][j][c] = 0.f;

    load_stage(0, 0); cpa_commit();
    load_stage(1, 1); cpa_commit();

    int st = 0;
    for (int i = 0; i < NT; i++) {
        cpa_wait1();
        __syncthreads();

        const float* asf = As + st * ASTG;
        const float* bsf = Bs + st * BSTG;
#pragma unroll
        for (int kk = 0; kk < 4; kk++) {
            unsigned af[4][4];
#pragma unroll
            for (int mt = 0; mt < 4; mt++) {
                int mb = wm0 + mt * 16;
                af[mt][0] = __float_as_uint(asf[(mb + g    ) * APITCH + kk * 8 + tig]);
                af[mt][1] = __float_as_uint(asf[(mb + 8 + g) * APITCH + kk * 8 + tig]);
                af[mt][2] = __float_as_uint(asf[(mb + g    ) * APITCH + kk * 8 + tig + 4]);
                af[mt][3] = __float_as_uint(asf[(mb + 8 + g) * APITCH + kk * 8 + tig + 4]);
            }
            unsigned bf[4][2];
#pragma unroll
            for (int nt = 0; nt < 4; nt++) {
                bf[nt][0] = __float_as_uint(bsf[(kk * 8 + tig    ) * BPITCH + wn0 + nt * 8 + g]);
                bf[nt][1] = __float_as_uint(bsf[(kk * 8 + tig + 4) * BPITCH + wn0 + nt * 8 + g]);
            }
#pragma unroll
            for (int mt = 0; mt < 4; mt++)
#pragma unroll
                for (int nt = 0; nt < 4; nt++) {
                    asm volatile(
                        "mma.sync.aligned.m16n8k8.row.col.f32.tf32.tf32.f32 "
                        "{%0,%1,%2,%3}, {%4,%5,%6,%7}, {%8,%9}, {%0,%1,%2,%3};\n"
                        : "+f"(acc[mt][nt][0]), "+f"(acc[mt][nt][1]),
                          "+f"(acc[mt][nt][2]), "+f"(acc[mt][nt][3])
                        : "r"(af[mt][0]), "r"(af[mt][1]), "r"(af[mt][2]), "r"(af[mt][3]),
                          "r"(bf[nt][0]), "r"(bf[nt][1]));
                }
        }

        if (i + 2 < NT) { load_stage(i + 2, (st + 2) % 3); }
        cpa_commit();
        st = (st + 1) % 3;
    }

#pragma unroll
    for (int mt = 0; mt < 4; mt++) {
#pragma unroll
        for (int nt = 0; nt < 4; nt++) {
            int r = row0 + wm0 + mt * 16 + g;
            int c = col0 + wn0 + nt * 8 + tig * 2;
            float b0v = bias[c], b1v = bias[c + 1];
            float2 v0 = make_float2(acc[mt][nt][0] + b0v, acc[mt][nt][1] + b1v);
            float2 v1 = make_float2(acc[mt][nt][2] + b0v, acc[mt][nt][3] + b1v);
            *(float2*)&C[(size_t)r * N + c] = v0;
            *(float2*)&C[(size_t)(r + 8) * N + c] = v1;
        }
    }
}
#define GEMM_SMEM (3 * (ASTG + BSTG) * 4)

// ======================= skinny split-K GEMM (M<=64) =======================
template<int M>
__global__ void gemm_skinny(const float* __restrict__ A, const float* __restrict__ W,
                            float* __restrict__ part, int N, int K)
{
    __shared__ float As[64][132];
    const int tid = threadIdx.x;
    const int ks = blockIdx.y;
    const int n  = blockIdx.x * 64 + (tid & 63);
    const int mg = tid >> 6;
    const int k0 = ks * 128;

    for (int idx = tid; idx < M * 32; idx += 256) {
        int m = idx >> 5, c4 = (idx & 31) * 4;
        *(float4*)&As[m][c4] = *(const float4*)&A[(size_t)m * K + k0 + c4];
    }
    __syncthreads();

    const int MR = M / 4;
    float acc[MR];
#pragma unroll
    for (int r = 0; r < MR; r++) acc[r] = 0.f;

#pragma unroll 4
    for (int k = 0; k < 128; k++) {
        float wv = __ldg(&W[(size_t)(k0 + k) * N + n]);
#pragma unroll
        for (int r = 0; r < MR; r++) acc[r] += As[mg + 4 * r][k] * wv;
    }
#pragma unroll
    for (int r = 0; r < MR; r++)
        part[((size_t)ks * 64 + mg + 4 * r) * N + n] = acc[r];
}

// dual variant: blockIdx.z selects (W, part); same A (M=64)
__global__ void gemm_skinny_dual(const float* __restrict__ A,
                                 const float* __restrict__ W0, const float* __restrict__ W1,
                                 float* __restrict__ p0, float* __restrict__ p1)
{
    __shared__ float As[64][132];
    const float* W = blockIdx.z ? W1 : W0;
    float* part    = blockIdx.z ? p1 : p0;
    const int tid = threadIdx.x;
    const int ks = blockIdx.y;
    const int n  = blockIdx.x * 64 + (tid & 63);
    const int mg = tid >> 6;
    const int k0 = ks * 128;

    for (int idx = tid; idx < 64 * 32; idx += 256) {
        int m = idx >> 5, c4 = (idx & 31) * 4;
        *(float4*)&As[m][c4] = *(const float4*)&A[(size_t)m * DD + k0 + c4];
    }
    __syncthreads();

    float acc[16];
#pragma unroll
    for (int r = 0; r < 16; r++) acc[r] = 0.f;
#pragma unroll 4
    for (int k = 0; k < 128; k++) {
        float wv = __ldg(&W[(size_t)(k0 + k) * DD + n]);
#pragma unroll
        for (int r = 0; r < 16; r++) acc[r] += As[mg + 4 * r][k] * wv;
    }
#pragma unroll
    for (int r = 0; r < 16; r++)
        part[((size_t)ks * 64 + mg + 4 * r) * DD + n] = acc[r];
}

__global__ void skinny_reduce(const float* __restrict__ part, const float* __restrict__ bias,
                              float* __restrict__ C, int M, int N)
{
    int i = blockIdx.x * 256 + threadIdx.x;
    if (i < M * N) {
        int n = i & (N - 1);
        int m = i / N;
        float s = bias[n];
#pragma unroll
        for (int z = 0; z < 8; z++) s += part[((size_t)z * 64 + m) * N + n];
        C[i] = s;
    }
}

__global__ void skinny_reduce_dual(const float* __restrict__ p0, const float* __restrict__ p1,
                                   const float* __restrict__ bias0, const float* __restrict__ bias1,
                                   float* __restrict__ C0, float* __restrict__ C1)
{
    int i = blockIdx.x * 256 + threadIdx.x;   // 64*DD
    const float* part = blockIdx.y ? p1 : p0;
    const float* bias = blockIdx.y ? bias1 : bias0;
    float* C          = blockIdx.y ? C1 : C0;
    int n = i & (DD - 1);
    int m = i / DD;
    float s = bias[n];
#pragma unroll
    for (int z = 0; z < 8; z++) s += part[((size_t)z * 64 + m) * DD + n];
    C[i] = s;
}

__global__ void skinny_reduce_addsq(const float* __restrict__ part, const float* __restrict__ bias,
                                    const float* __restrict__ sq, float* __restrict__ C)
{
    int i = blockIdx.x * 256 + threadIdx.x;
    int n = i & (DD - 1);
    int m = i / DD;
    float s = bias[n] + sq[i % (NS * DD)];
#pragma unroll
    for (int z = 0; z < 8; z++) s += part[((size_t)z * 64 + m) * DD + n];
    C[i] = s;
}

// ======================= dispatch attention =======================
__global__ void disp_scores(const float* __restrict__ qh, const float* __restrict__ kh,
                            float* __restrict__ sc)
{
    __shared__ float q[16][64];
    __shared__ float kt[128][65];
    const int j0 = blockIdx.x * 128;
    const int h  = blockIdx.y;
    const int b  = blockIdx.z;
    const int tid = threadIdx.x;

    for (int i = tid; i < NS * DH; i += 256) {
        int s = i >> 6, d = i & 63;
        q[s][d] = qh[(size_t)s * DD + h * DH + d];
    }
#pragma unroll
    for (int p = 0; p < 8; p++) {
        int idx = tid + p * 256;
        int jj = idx >> 4, d4 = (idx & 15) * 4;
        float4 v = *(const float4*)&kh[((size_t)b * LL + j0 + jj) * DD + h * DH + d4];
        kt[jj][d4 + 0] = v.x; kt[jj][d4 + 1] = v.y;
        kt[jj][d4 + 2] = v.z; kt[jj][d4 + 3] = v.w;
    }
    __syncthreads();

#pragma unroll
    for (int p = 0; p < 8; p++) {
        int idx = tid + p * 256;
        int s = idx >> 7, jj = idx & 127;
        float dot = 0.f;
#pragma unroll
        for (int d = 0; d < DH; d++) dot += q[s][d] * kt[jj][d];
        sc[(((size_t)b * HH + h) * NS + s) * LL + j0 + jj] = dot * 0.125f;
    }
}

__global__ void disp_softmax(float* __restrict__ sc)
{
    __shared__ float red[9];
    const int tid = threadIdx.x;
    float* r = sc + (size_t)blockIdx.x * LL;
    float v[8];
    float mx = -1e30f;
#pragma unroll
    for (int i = 0; i < 8; i++) { v[i] = r[tid + i * 256]; mx = fmaxf(mx, v[i]); }
#pragma unroll
    for (int o = 16; o; o >>= 1) mx = fmaxf(mx, __shfl_xor_sync(0xffffffffu, mx, o));
    int wd = tid >> 5, ln = tid & 31;
    if (!ln) red[wd] = mx;
    __syncthreads();
    if (tid < 32) {
        mx = (ln < 8) ? red[ln] : -1e30f;
#pragma unroll
        for (int o = 4; o; o >>= 1) mx = fmaxf(mx, __shfl_xor_sync(0xffffffffu, mx, o));
        if (!ln) red[8] = mx;
    }
    __syncthreads();
    mx = red[8];
    float sum = 0.f;
#pragma unroll
    for (int i = 0; i < 8; i++) { v[i] = __expf(v[i] - mx); sum += v[i]; }
#pragma unroll
    for (int o = 16; o; o >>= 1) sum += __shfl_xor_sync(0xffffffffu, sum, o);
    __syncthreads();
    if (!ln) red[wd] = sum;
    __syncthreads();
    if (tid < 32) {
        sum = (ln < 8) ? red[ln] : 0.f;
#pragma unroll
        for (int o = 4; o; o >>= 1) sum += __shfl_xor_sync(0xffffffffu, sum, o);
        if (!ln) red[8] = sum;
    }
    __syncthreads();
    float inv = 1.f / red[8];
#pragma unroll
    for (int i = 0; i < 8; i++) r[tid + i * 256] = v[i] * inv;
}

__global__ void disp_av(const float* __restrict__ sc, const float* __restrict__ vh,
                        float* __restrict__ part)
{
    __shared__ float p[16][132];
    __shared__ float vt[128][65];
    const int h = blockIdx.x, b = blockIdx.y, jz = blockIdx.z;
    const int j0 = jz * 128;
    const int tid = threadIdx.x;

#pragma unroll
    for (int q = 0; q < 2; q++) {
        int idx = tid + q * 256;
        int s = idx >> 5, j4 = (idx & 31) * 4;
        float4 v = *(const float4*)&sc[(((size_t)b * HH + h) * NS + s) * LL + j0 + j4];
        *(float4*)&p[s][j4] = v;
    }
#pragma unroll
    for (int q = 0; q < 8; q++) {
        int idx = tid + q * 256;
        int jj = idx >> 4, d4 = (idx & 15) * 4;
        float4 v = *(const float4*)&vh[((size_t)b * LL + j0 + jj) * DD + h * DH + d4];
        vt[jj][d4 + 0] = v.x; vt[jj][d4 + 1] = v.y;
        vt[jj][d4 + 2] = v.z; vt[jj][d4 + 3] = v.w;
    }
    __syncthreads();

    float acc[4] = {0.f, 0.f, 0.f, 0.f};
#pragma unroll 4
    for (int jj = 0; jj < 128; jj++) {
#pragma unroll
        for (int k = 0; k < 4; k++) {
            int idx = tid + k * 256;
            int s = idx >> 6, d = idx & 63;
            acc[k] += p[s][jj] * vt[jj][d];
        }
    }
#pragma unroll
    for (int k = 0; k < 4; k++) {
        int idx = tid + k * 256;
        int s = idx >> 6, d = idx & 63;
        part[(size_t)jz * (BB * NS * DD) + ((size_t)b * NS + s) * DD + h * DH + d] = acc[k];
    }
}

__global__ void disp_reduce(const float* __restrict__ part, float* __restrict__ att1)
{
    int i = blockIdx.x * 256 + threadIdx.x;
    float s = 0.f;
#pragma unroll
    for (int z = 0; z < 16; z++) s += part[(size_t)z * (BB * NS * DD) + i];
    att1[i] = s;
}

// ---------------- layernorm ----------------
__global__ void ln_kernel(const float* __restrict__ inp, const float* __restrict__ gam,
                          const float* __restrict__ bet, float* __restrict__ outp)
{
    const int row = blockIdx.x;
    const int e = row & (NS - 1);
    const float* xr = inp + (size_t)row * DD;
    __shared__ float r1[8], r2[8];
    float s1 = 0.f, s2 = 0.f;
    for (int d = threadIdx.x; d < DD; d += 256) {
        float v = xr[d];
        s1 += v; s2 += v * v;
    }
#pragma unroll
    for (int o = 16; o; o >>= 1) {
        s1 += __shfl_xor_sync(0xffffffffu, s1, o);
        s2 += __shfl_xor_sync(0xffffffffu, s2, o);
    }
    int wid = threadIdx.x >> 5, lane = threadIdx.x & 31;
    if (!lane) { r1[wid] = s1; r2[wid] = s2; }
    __syncthreads();
    if (threadIdx.x < 32) {
        s1 = (lane < 8) ? r1[lane] : 0.f;
        s2 = (lane < 8) ? r2[lane] : 0.f;
#pragma unroll
        for (int o = 4; o; o >>= 1) {
            s1 += __shfl_xor_sync(0xffffffffu, s1, o);
            s2 += __shfl_xor_sync(0xffffffffu, s2, o);
        }
        if (!lane) { r1[0] = s1; r2[0] = s2; }
    }
    __syncthreads();
    float mu  = r1[0] * (1.f / DD);
    float var = r2[0] * (1.f / DD) - mu * mu;
    float inv = rsqrtf(var + 1e-5f);
    for (int d = threadIdx.x; d < DD; d += 256)
        outp[(size_t)row * DD + d] = (xr[d] - mu) * inv * gam[(size_t)e * DD + d] + bet[(size_t)e * DD + d];
}

__device__ __forceinline__ float silu_f(float x) { return x / (1.f + __expf(-x)); }

// ---------------- expert up/gate ----------------
__global__ void expert_ug(const float* __restrict__ hn,
                          const float* __restrict__ W1, const float* __restrict__ b1,
                          const float* __restrict__ Wg, const float* __restrict__ bg,
                          float* __restrict__ ug)
{
    const int e = blockIdx.y;
    const int f = blockIdx.x * 128 + threadIdx.x;
    __shared__ float hs[BB][DD];
    for (int i = threadIdx.x; i < BB * DD / 4; i += 128) {
        int b = (i * 4) >> 10, d4 = (i * 4) & 1023;
        *(float4*)&hs[b][d4] = *(const float4*)&hn[((size_t)b * NS + e) * DD + d4];
    }
    __syncthreads();

    const float* w1 = W1 + (size_t)e * DD * FF + f;
    const float* wg = Wg + (size_t)e * DD * FF + f;
    float au[BB] = {0.f, 0.f, 0.f, 0.f};
    float ag[BB] = {0.f, 0.f, 0.f, 0.f};
#pragma unroll 16
    for (int d = 0; d < DD; d++) {
        float w1v = ldcs(&w1[(size_t)d * FF]);
        float wgv = ldcs(&wg[(size_t)d * FF]);
#pragma unroll
        for (int b = 0; b < BB; b++) {
            float hv = hs[b][d];
            au[b] += hv * w1v;
            ag[b] += hv * wgv;
        }
    }
    float bu = b1[(size_t)e * FF + f];
    float bv = bg[(size_t)e * FF + f];
#pragma unroll
    for (int b = 0; b < BB; b++)
        ug[((size_t)b * EE + e) * FF + f] = silu_f(au[b] + bu) * silu_f(ag[b] + bv);
}

// ---------------- expert down: split-F partials ----------------
__global__ void expert_w2p(const float* __restrict__ ug, const float* __restrict__ W2,
                           float* __restrict__ part)
{
    __shared__ float us[BB][512];
    const int e = blockIdx.y, fz = blockIdx.z;
    const int d = blockIdx.x * 128 + threadIdx.x;
    for (int i = threadIdx.x; i < BB * 512 / 4; i += 128) {
        int b = (i * 4) >> 9, f4 = (i * 4) & 511;
        *(float4*)&us[b][f4] = *(const float4*)&ug[((size_t)b * EE + e) * FF + fz * 512 + f4];
    }
    __syncthreads();
    const float* w = W2 + ((size_t)e * FF + fz * 512) * DD + d;
    float acc[BB] = {0.f, 0.f, 0.f, 0.f};
#pragma unroll 16
    for (int f = 0; f < 512; f++) {
        float wv = ldcs(&w[(size_t)f * DD]);
#pragma unroll
        for (int b = 0; b < BB; b++) acc[b] += us[b][f] * wv;
    }
#pragma unroll
    for (int b = 0; b < BB; b++)
        part[(size_t)fz * (BB * EE * DD) + ((size_t)b * EE + e) * DD + d] = acc[b];
}

__global__ void w2_reduce(const float* __restrict__ part, const float* __restrict__ b2,
                          float* __restrict__ o)
{
    int i = blockIdx.x * 256 + threadIdx.x;
    int d = i & 1023;
    int e = (i >> 10) & 15;
    float s = b2[(size_t)e * DD + d];
#pragma unroll
    for (int z = 0; z < 8; z++) s += part[(size_t)z * (BB * EE * DD) + i];
    o[i] += s;
}

// ---------------- combine attention (output pre-rounded to tf32) ----------------
__global__ void combine_attn(const float* __restrict__ qh, const float* __restrict__ kh,
                             const float* __restrict__ vh, float* __restrict__ out)
{
    extern __shared__ float sm[];
    const int PITCH = HH * 65;
    float* qsm = sm;
    float* ksm = sm + 16 * PITCH;
    float* vsm = sm + 32 * PITCH;
    const int b  = blockIdx.y;
    const int t0 = blockIdx.x * 16;
    const int tid = threadIdx.x;

    for (int i = tid; i < NS * DD; i += 256) {
        int r = i >> 10, hd = i & 1023;
        int h = hd >> 6, d = hd & 63;
        int sw = r * PITCH + h * 65 + d;
        ksm[sw] = kh[(size_t)b * NS * DD + i];
        vsm[sw] = vh[(size_t)b * NS * DD + i];
        qsm[sw] = qh[((size_t)b * LL + t0) * DD + i];
    }
    __syncthreads();

    const int tt = tid >> 4;
    const int h  = tid & 15;

    float qreg[DH];
#pragma unroll
    for (int d = 0; d < DH; d++) qreg[d] = qsm[tt * PITCH + h * 65 + d];

    float sco[NS];
    float mx = -1e30f;
#pragma unroll
    for (int s = 0; s < NS; s++) {
        const float* kp = &ksm[s * PITCH + h * 65];
        float dot = 0.f;
#pragma unroll
        for (int d = 0; d < DH; d++) dot += qreg[d] * kp[d];
        dot *= 0.125f;
        sco[s] = dot;
        mx = fmaxf(mx, dot);
    }
    float sum = 0.f;
#pragma unroll
    for (int s = 0; s < NS; s++) { sco[s] = __expf(sco[s] - mx); sum += sco[s]; }
    float inv = 1.f / sum;

    float ov[DH];
#pragma unroll
    for (int d = 0; d < DH; d++) ov[d] = 0.f;
#pragma unroll
    for (int s = 0; s < NS; s++) {
        float pr = sco[s] * inv;
        const float* vp = &vsm[s * PITCH + h * 65];
#pragma unroll
        for (int d = 0; d < DH; d++) ov[d] += pr * vp[d];
    }
    __syncthreads();
#pragma unroll
    for (int d = 0; d < DH; d++) qsm[tt * PITCH + h * 65 + d] = ov[d];
    __syncthreads();
    for (int i = tid; i < NS * DD; i += 256) {
        int r = i >> 10, hd = i & 1023;
        int hh = hd >> 6, d = hd & 63;
        out[((size_t)b * LL + t0) * DD + i] = f2tf32f(qsm[r * PITCH + hh * 65 + d]);
    }
}

// ---------------- host launch ----------------
extern "C" void kernel_launch(void* const* d_in, const int* in_sizes, int n_in,
                              void* d_out, int out_size)
{
    const float* x    = (const float*)d_in[0];
    const float* sq   = (const float*)d_in[1];
    const float* dWq  = (const float*)d_in[2];
    const float* dWk  = (const float*)d_in[3];
    const float* dWv  = (const float*)d_in[4];
    const float* dWo  = (const float*)d_in[5];
    const float* dbq  = (const float*)d_in[6];
    const float* dbk  = (const float*)d_in[7];
    const float* dbv  = (const float*)d_in[8];
    const float* dbo  = (const float*)d_in[9];
    const float* cWq  = (const float*)d_in[10];
    const float* cWk  = (const float*)d_in[11];
    const float* cWv  = (const float*)d_in[12];
    const float* cWo  = (const float*)d_in[13];
    const float* cbq  = (const float*)d_in[14];
    const float* cbk  = (const float*)d_in[15];
    const float* cbv  = (const float*)d_in[16];
    const float* cbo  = (const float*)d_in[17];
    const float* elng = (const float*)d_in[18];
    const float* elnb = (const float*)d_in[19];
    const float* eW1  = (const float*)d_in[20];
    const float* eb1  = (const float*)d_in[21];
    const float* eWg  = (const float*)d_in[22];
    const float* ebg  = (const float*)d_in[23];
    const float* eW2  = (const float*)d_in[24];
    const float* eb2  = (const float*)d_in[25];
    float* out = (float*)d_out;

    float *kh, *vh, *qh1, *att1, *o, *hn, *ug, *qh2, *kh2, *vh2, *att2;
    float *sc, *avp, *skp, *w2p, *xtf, *wtf;
    cudaGetSymbolAddress((void**)&kh,   g_kh);
    cudaGetSymbolAddress((void**)&vh,   g_vh);
    cudaGetSymbolAddress((void**)&qh1,  g_qh1);
    cudaGetSymbolAddress((void**)&att1, g_att1);
    cudaGetSymbolAddress((void**)&o,    g_o);
    cudaGetSymbolAddress((void**)&hn,   g_hn);
    cudaGetSymbolAddress((void**)&ug,   g_ug);
    cudaGetSymbolAddress((void**)&qh2,  g_qh2);
    cudaGetSymbolAddress((void**)&kh2,  g_kh2);
    cudaGetSymbolAddress((void**)&vh2,  g_vh2);
    cudaGetSymbolAddress((void**)&att2, g_att2);
    cudaGetSymbolAddress((void**)&sc,   g_sc);
    cudaGetSymbolAddress((void**)&avp,  g_part);
    cudaGetSymbolAddress((void**)&skp,  g_skp);
    cudaGetSymbolAddress((void**)&w2p,  g_w2p);
    cudaGetSymbolAddress((void**)&xtf,  g_xtf);
    cudaGetSymbolAddress((void**)&wtf,  g_wtf);

    static cudaStream_t s2 = nullptr;
    static cudaEvent_t ev0, evKH, evVH, evPipe;
    if (!s2) {
        cudaStreamCreateWithFlags(&s2, cudaStreamNonBlocking);
        cudaEventCreateWithFlags(&ev0,   cudaEventDisableTiming);
        cudaEventCreateWithFlags(&evKH,  cudaEventDisableTiming);
        cudaEventCreateWithFlags(&evVH,  cudaEventDisableTiming);
        cudaEventCreateWithFlags(&evPipe,cudaEventDisableTiming);
    }

    const int SMEM_COMB = 3 * 16 * (HH * 65) * 4;
    cudaFuncSetAttribute(combine_attn, cudaFuncAttributeMaxDynamicSharedMemorySize, SMEM_COMB);
    cudaFuncSetAttribute(gemm_tf32, cudaFuncAttributeMaxDynamicSharedMemorySize, GEMM_SMEM);

    dim3 gBig(DD / 128, (BB * LL) / 128);
    dim3 gSk(DD / 64, 8);
    const int W4 = DD * DD / 4;
    const int X4 = BB * LL * DD / 4;

    cudaEventRecord(ev0, 0);

    // L: conversions then serial GEMM chain (kh first: it gates the pipeline)
    cvt_tf32<<<X4 / 256, 256>>>(x, xtf, X4);                                       // 1
    cvt_w4<<<dim3(W4 / 256, 4), 256>>>(dWk, dWv, cWq, cWo, wtf);                   // 2

    // s2: dispatch Q projection (independent of x)
    cudaStreamWaitEvent(s2, ev0, 0);
    gemm_skinny<16><<<gSk, 256, 0, s2>>>(sq, dWq, skp, DD, DD);                    // 3

    gemm_tf32<<<gBig, 256, GEMM_SMEM>>>(xtf, wtf + 0 * DD * DD, dbk, kh, BB * LL, DD, DD);  // 4 <- profiled
    cudaEventRecord(evKH, 0);

    skinny_reduce<<<(16 * DD) / 256, 256, 0, s2>>>(skp, dbq, qh1, 16, DD);         // 5

    gemm_tf32<<<gBig, 256, GEMM_SMEM>>>(xtf, wtf + 1 * DD * DD, dbv, vh, BB * LL, DD, DD);  // 6
    cudaEventRecord(evVH, 0);
    gemm_tf32<<<gBig, 256, GEMM_SMEM>>>(xtf, wtf + 2 * DD * DD, cbq, qh2, BB * LL, DD, DD); // 7

    // s2: dispatch attention -> experts -> combine projections (overlaps vh/qh2 GEMMs)
    cudaStreamWaitEvent(s2, evKH, 0);
    disp_scores<<<dim3(LL / 128, HH, BB), 256, 0, s2>>>(qh1, kh, sc);
    disp_softmax<<<BB * HH * NS, 256, 0, s2>>>(sc);
    cudaStreamWaitEvent(s2, evVH, 0);
    disp_av<<<dim3(HH, BB, 16), 256, 0, s2>>>(sc, vh, avp);
    disp_reduce<<<(BB * NS * DD) / 256, 256, 0, s2>>>(avp, att1);

    gemm_skinny<64><<<gSk, 256, 0, s2>>>(att1, dWo, skp, DD, DD);
    skinny_reduce_addsq<<<(64 * DD) / 256, 256, 0, s2>>>(skp, dbo, sq, o);

    ln_kernel<<<BB * NS, 256, 0, s2>>>(o, elng, elnb, hn);
    expert_ug<<<dim3(FF / 128, EE), 128, 0, s2>>>(hn, eW1, eb1, eWg, ebg, ug);
    expert_w2p<<<dim3(DD / 128, EE, 8), 128, 0, s2>>>(ug, eW2, w2p);
    w2_reduce<<<(BB * EE * DD) / 256, 256, 0, s2>>>(w2p, eb2, o);

    // combine K/V projections (dual: 2 launches instead of 4)
    gemm_skinny_dual<<<dim3(DD / 64, 8, 2), 256, 0, s2>>>(o, cWk, cWv, skp, w2p);
    skinny_reduce_dual<<<dim3((64 * DD) / 256, 2), 256, 0, s2>>>(skp, w2p, cbk, cbv, kh2, vh2);
    cudaEventRecord(evPipe, s2);

    // L: join -> combine attention + final projection
    cudaStreamWaitEvent(0, evPipe, 0);
    combine_attn<<<dim3(LL / 16, BB), 256, SMEM_COMB>>>(qh2, kh2, vh2, att2);
    gemm_tf32<<<gBig, 256, GEMM_SMEM>>>(att2, wtf + 3 * DD * DD, cbo, out, BB * LL, DD, DD);
}

// round 7
// speedup vs baseline: 1.8375x; 1.2832x over previous
#include <cuda_runtime.h>
#include <cuda_fp16.h>
#include <math.h>

#define BB 4
#define LL 2048
#define DD 1024
#define HH 16
#define DH 64
#define NS 16
#define EE 16
#define FF 4096

// ---------------- scratch ----------------
__device__ float  g_kh  [BB*LL*DD];
__device__ float  g_vh  [BB*LL*DD];
__device__ float  g_qh1 [NS*DD];
__device__ float  g_att1[BB*NS*DD];
__device__ float  g_o   [BB*NS*DD];
__device__ float  g_hn  [BB*NS*DD];
__device__ float  g_ug  [BB*EE*FF];
__device__ float  g_qh2 [BB*LL*DD];
__device__ float  g_kh2 [BB*NS*DD];
__device__ float  g_vh2 [BB*NS*DD];
__device__ float  g_sc  [BB*HH*NS*LL];
__device__ float  g_part[16*BB*NS*DD];
__device__ float  g_skp [8*64*DD];
__device__ float  g_w2p [8*BB*EE*DD];
__device__ __half g_xh  [BB*LL*DD];     // x in fp16
__device__ __half g_wh  [4*DD*DD];      // dWk,dWv,cWq,cWo in fp16
__device__ __half g_a2h [BB*LL*DD];     // combine-attn output in fp16

__device__ __forceinline__ void cpa16(void* dst, const void* src) {
    unsigned d = (unsigned)__cvta_generic_to_shared(dst);
    asm volatile("cp.async.cg.shared.global [%0], [%1], 16;\n" :: "r"(d), "l"(src));
}
__device__ __forceinline__ void cpa_commit() {
    asm volatile("cp.async.commit_group;\n" ::: "memory");
}
__device__ __forceinline__ void cpa_wait2() {
    asm volatile("cp.async.wait_group 2;\n" ::: "memory");
}

__device__ __forceinline__ float ldcs(const float* p) {
    float v;
    asm volatile("ld.global.cs.f32 %0, [%1];" : "=f"(v) : "l"(p));
    return v;
}

// ---------------- fp16 conversion pre-passes ----------------
__global__ void cvt_f16(const float* __restrict__ src, __half* __restrict__ dst, int n4)
{
    int i = blockIdx.x * 256 + threadIdx.x;
    if (i < n4) {
        float4 v = *(const float4*)&src[(size_t)i * 4];
        __half2 h0 = __floats2half2_rn(v.x, v.y);
        __half2 h1 = __floats2half2_rn(v.z, v.w);
        __half2* d2 = (__half2*)(dst + (size_t)i * 4);
        d2[0] = h0; d2[1] = h1;
    }
}

__global__ void cvt_w4_f16(const float* __restrict__ s0, const float* __restrict__ s1,
                           const float* __restrict__ s2, const float* __restrict__ s3,
                           __half* __restrict__ dst)
{
    int i = blockIdx.x * 256 + threadIdx.x;
    int y = blockIdx.y;
    const float* s = (y == 0) ? s0 : (y == 1) ? s1 : (y == 2) ? s2 : s3;
    float4 v = *(const float4*)&s[(size_t)i * 4];
    __half2 h0 = __floats2half2_rn(v.x, v.y);
    __half2 h1 = __floats2half2_rn(v.z, v.w);
    __half2* d2 = (__half2*)(dst + (size_t)y * DD * DD + (size_t)i * 4);
    d2[0] = h0; d2[1] = h1;
}

// ======================= fp16 tensor-core GEMM (m16n8k16 + ldmatrix) =======================
// C[M,N](f32) = A[M,K](f16) @ W[K,N](f16) + bias[N].  M%128==0, N%128==0, K%32==0.
// 128x128x32 tile, 256 threads (8 warps 2x4, warp tile 64x32), 4-stage cp.async.
#define APITCH_H 40
#define BPITCH_H 136
#define ASTG_H (128*APITCH_H)    // halfs
#define BSTG_H (32*BPITCH_H)
#define GEMM_SMEM_H (4 * (ASTG_H + BSTG_H) * 2)

__global__ __launch_bounds__(256)
void gemm_f16(const __half* __restrict__ A, const __half* __restrict__ W,
              const float* __restrict__ bias, float* __restrict__ C,
              int M, int N, int K)
{
    extern __shared__ __half smh[];
    __half* As = smh;                   // [4][128][APITCH_H]
    __half* Bs = smh + 4 * ASTG_H;      // [4][32][BPITCH_H]

    const int tid  = threadIdx.x;
    const int wid  = tid >> 5;
    const int lane = tid & 31;
    const int g    = lane >> 2;
    const int tig  = lane & 3;
    const int wm0  = (wid >> 2) * 64;
    const int wn0  = (wid & 3) * 32;
    const int row0 = blockIdx.y * 128;
    const int col0 = blockIdx.x * 128;

    const int la = lane & 15;          // ldmatrix row-within-16
    const int lb = (lane >> 4) * 8;    // ldmatrix col-half offset

    const unsigned smem_base = (unsigned)__cvta_generic_to_shared(smh);
    const unsigned bs_base   = smem_base + 4 * ASTG_H * 2;

    const int NT = K >> 5;

    auto load_stage = [&](int tile, int st) {
        const int k0 = tile * 32;
        __half* as = As + st * ASTG_H;
        __half* bs = Bs + st * BSTG_H;
#pragma unroll
        for (int p = 0; p < 2; p++) {
            int c = tid + p * 256;
            int ar = c >> 2, ac = (c & 3) * 8;
            cpa16(&as[ar * APITCH_H + ac], &A[(size_t)(row0 + ar) * K + k0 + ac]);
            int br = c >> 4, bc = (c & 15) * 8;
            cpa16(&bs[br * BPITCH_H + bc], &W[(size_t)(k0 + br) * N + col0 + bc]);
        }
    };

    float acc[4][4][4];
#pragma unroll
    for (int i = 0; i < 4; i++)
#pragma unroll
        for (int j = 0; j < 4; j++)
#pragma unroll
            for (int c = 0; c < 4; c++) acc[i][j][c] = 0.f;

    load_stage(0, 0); cpa_commit();
    load_stage(1, 1); cpa_commit();
    load_stage(2, 2); cpa_commit();

    for (int i = 0; i < NT; i++) {
        cpa_wait2();
        __syncthreads();

        const int st = i & 3;
        const unsigned aBase = smem_base + (st * ASTG_H) * 2;
        const unsigned bBase = bs_base   + (st * BSTG_H) * 2;

#pragma unroll
        for (int ks = 0; ks < 2; ks++) {
            unsigned af[4][4];
#pragma unroll
            for (int mt = 0; mt < 4; mt++) {
                unsigned addr = aBase + (((wm0 + mt * 16 + la) * APITCH_H) + ks * 16 + lb) * 2;
                asm volatile("ldmatrix.sync.aligned.m8n8.x4.shared.b16 {%0,%1,%2,%3}, [%4];"
                             : "=r"(af[mt][0]), "=r"(af[mt][1]), "=r"(af[mt][2]), "=r"(af[mt][3])
                             : "r"(addr));
            }
            unsigned bf[4][2];
#pragma unroll
            for (int np = 0; np < 2; np++) {
                unsigned addr = bBase + (((ks * 16 + la) * BPITCH_H) + wn0 + np * 16 + lb) * 2;
                asm volatile("ldmatrix.sync.aligned.m8n8.x4.trans.shared.b16 {%0,%1,%2,%3}, [%4];"
                             : "=r"(bf[np * 2][0]), "=r"(bf[np * 2][1]),
                               "=r"(bf[np * 2 + 1][0]), "=r"(bf[np * 2 + 1][1])
                             : "r"(addr));
            }
#pragma unroll
            for (int mt = 0; mt < 4; mt++)
#pragma unroll
                for (int nt = 0; nt < 4; nt++) {
                    asm volatile(
                        "mma.sync.aligned.m16n8k16.row.col.f32.f16.f16.f32 "
                        "{%0,%1,%2,%3}, {%4,%5,%6,%7}, {%8,%9}, {%0,%1,%2,%3};\n"
                        : "+f"(acc[mt][nt][0]), "+f"(acc[mt][nt][1]),
                          "+f"(acc[mt][nt][2]), "+f"(acc[mt][nt][3])
                        : "r"(af[mt][0]), "r"(af[mt][1]), "r"(af[mt][2]), "r"(af[mt][3]),
                          "r"(bf[nt][0]), "r"(bf[nt][1]));
                }
        }

        if (i + 3 < NT) load_stage(i + 3, (i + 3) & 3);
        cpa_commit();
    }

#pragma unroll
    for (int mt = 0; mt < 4; mt++) {
#pragma unroll
        for (int nt = 0; nt < 4; nt++) {
            int r = row0 + wm0 + mt * 16 + g;
            int c = col0 + wn0 + nt * 8 + tig * 2;
            float b0v = bias[c], b1v = bias[c + 1];
            float2 v0 = make_float2(acc[mt][nt][0] + b0v, acc[mt][nt][1] + b1v);
            float2 v1 = make_float2(acc[mt][nt][2] + b0v, acc[mt][nt][3] + b1v);
            *(float2*)&C[(size_t)r * N + c] = v0;
            *(float2*)&C[(size_t)(r + 8) * N + c] = v1;
        }
    }
}

// ======================= skinny split-K GEMM (M<=64, f32) =======================
template<int M>
__global__ void gemm_skinny(const float* __restrict__ A, const float* __restrict__ W,
                            float* __restrict__ part, int N, int K)
{
    __shared__ float As[64][132];
    const int tid = threadIdx.x;
    const int ks = blockIdx.y;
    const int n  = blockIdx.x * 64 + (tid & 63);
    const int mg = tid >> 6;
    const int k0 = ks * 128;

    for (int idx = tid; idx < M * 32; idx += 256) {
        int m = idx >> 5, c4 = (idx & 31) * 4;
        *(float4*)&As[m][c4] = *(const float4*)&A[(size_t)m * K + k0 + c4];
    }
    __syncthreads();

    const int MR = M / 4;
    float acc[MR];
#pragma unroll
    for (int r = 0; r < MR; r++) acc[r] = 0.f;

#pragma unroll 4
    for (int k = 0; k < 128; k++) {
        float wv = __ldg(&W[(size_t)(k0 + k) * N + n]);
#pragma unroll
        for (int r = 0; r < MR; r++) acc[r] += As[mg + 4 * r][k] * wv;
    }
#pragma unroll
    for (int r = 0; r < MR; r++)
        part[((size_t)ks * 64 + mg + 4 * r) * N + n] = acc[r];
}

__global__ void gemm_skinny_dual(const float* __restrict__ A,
                                 const float* __restrict__ W0, const float* __restrict__ W1,
                                 float* __restrict__ p0, float* __restrict__ p1)
{
    __shared__ float As[64][132];
    const float* W = blockIdx.z ? W1 : W0;
    float* part    = blockIdx.z ? p1 : p0;
    const int tid = threadIdx.x;
    const int ks = blockIdx.y;
    const int n  = blockIdx.x * 64 + (tid & 63);
    const int mg = tid >> 6;
    const int k0 = ks * 128;

    for (int idx = tid; idx < 64 * 32; idx += 256) {
        int m = idx >> 5, c4 = (idx & 31) * 4;
        *(float4*)&As[m][c4] = *(const float4*)&A[(size_t)m * DD + k0 + c4];
    }
    __syncthreads();

    float acc[16];
#pragma unroll
    for (int r = 0; r < 16; r++) acc[r] = 0.f;
#pragma unroll 4
    for (int k = 0; k < 128; k++) {
        float wv = __ldg(&W[(size_t)(k0 + k) * DD + n]);
#pragma unroll
        for (int r = 0; r < 16; r++) acc[r] += As[mg + 4 * r][k] * wv;
    }
#pragma unroll
    for (int r = 0; r < 16; r++)
        part[((size_t)ks * 64 + mg + 4 * r) * DD + n] = acc[r];
}

__global__ void skinny_reduce(const float* __restrict__ part, const float* __restrict__ bias,
                              float* __restrict__ C, int M, int N)
{
    int i = blockIdx.x * 256 + threadIdx.x;
    if (i < M * N) {
        int n = i & (N - 1);
        int m = i / N;
        float s = bias[n];
#pragma unroll
        for (int z = 0; z < 8; z++) s += part[((size_t)z * 64 + m) * N + n];
        C[i] = s;
    }
}

__global__ void skinny_reduce_dual(const float* __restrict__ p0, const float* __restrict__ p1,
                                   const float* __restrict__ bias0, const float* __restrict__ bias1,
                                   float* __restrict__ C0, float* __restrict__ C1)
{
    int i = blockIdx.x * 256 + threadIdx.x;
    const float* part = blockIdx.y ? p1 : p0;
    const float* bias = blockIdx.y ? bias1 : bias0;
    float* C          = blockIdx.y ? C1 : C0;
    int n = i & (DD - 1);
    int m = i / DD;
    float s = bias[n];
#pragma unroll
    for (int z = 0; z < 8; z++) s += part[((size_t)z * 64 + m) * DD + n];
    C[i] = s;
}

__global__ void skinny_reduce_addsq(const float* __restrict__ part, const float* __restrict__ bias,
                                    const float* __restrict__ sq, float* __restrict__ C)
{
    int i = blockIdx.x * 256 + threadIdx.x;
    int n = i & (DD - 1);
    int m = i / DD;
    float s = bias[n] + sq[i % (NS * DD)];
#pragma unroll
    for (int z = 0; z < 8; z++) s += part[((size_t)z * 64 + m) * DD + n];
    C[i] = s;
}

// ======================= dispatch attention =======================
__global__ void disp_scores(const float* __restrict__ qh, const float* __restrict__ kh,
                            float* __restrict__ sc)
{
    __shared__ float q[16][64];
    __shared__ float kt[128][65];
    const int j0 = blockIdx.x * 128;
    const int h  = blockIdx.y;
    const int b  = blockIdx.z;
    const int tid = threadIdx.x;

    for (int i = tid; i < NS * DH; i += 256) {
        int s = i >> 6, d = i & 63;
        q[s][d] = qh[(size_t)s * DD + h * DH + d];
    }
#pragma unroll
    for (int p = 0; p < 8; p++) {
        int idx = tid + p * 256;
        int jj = idx >> 4, d4 = (idx & 15) * 4;
        float4 v = *(const float4*)&kh[((size_t)b * LL + j0 + jj) * DD + h * DH + d4];
        kt[jj][d4 + 0] = v.x; kt[jj][d4 + 1] = v.y;
        kt[jj][d4 + 2] = v.z; kt[jj][d4 + 3] = v.w;
    }
    __syncthreads();

#pragma unroll
    for (int p = 0; p < 8; p++) {
        int idx = tid + p * 256;
        int s = idx >> 7, jj = idx & 127;
        float dot = 0.f;
#pragma unroll
        for (int d = 0; d < DH; d++) dot += q[s][d] * kt[jj][d];
        sc[(((size_t)b * HH + h) * NS + s) * LL + j0 + jj] = dot * 0.125f;
    }
}

__global__ void disp_softmax(float* __restrict__ sc)
{
    __shared__ float red[9];
    const int tid = threadIdx.x;
    float* r = sc + (size_t)blockIdx.x * LL;
    float v[8];
    float mx = -1e30f;
#pragma unroll
    for (int i = 0; i < 8; i++) { v[i] = r[tid + i * 256]; mx = fmaxf(mx, v[i]); }
#pragma unroll
    for (int o = 16; o; o >>= 1) mx = fmaxf(mx, __shfl_xor_sync(0xffffffffu, mx, o));
    int wd = tid >> 5, ln = tid & 31;
    if (!ln) red[wd] = mx;
    __syncthreads();
    if (tid < 32) {
        mx = (ln < 8) ? red[ln] : -1e30f;
#pragma unroll
        for (int o = 4; o; o >>= 1) mx = fmaxf(mx, __shfl_xor_sync(0xffffffffu, mx, o));
        if (!ln) red[8] = mx;
    }
    __syncthreads();
    mx = red[8];
    float sum = 0.f;
#pragma unroll
    for (int i = 0; i < 8; i++) { v[i] = __expf(v[i] - mx); sum += v[i]; }
#pragma unroll
    for (int o = 16; o; o >>= 1) sum += __shfl_xor_sync(0xffffffffu, sum, o);
    __syncthreads();
    if (!ln) red[wd] = sum;
    __syncthreads();
    if (tid < 32) {
        sum = (ln < 8) ? red[ln] : 0.f;
#pragma unroll
        for (int o = 4; o; o >>= 1) sum += __shfl_xor_sync(0xffffffffu, sum, o);
        if (!ln) red[8] = sum;
    }
    __syncthreads();
    float inv = 1.f / red[8];
#pragma unroll
    for (int i = 0; i < 8; i++) r[tid + i * 256] = v[i] * inv;
}

__global__ void disp_av(const float* __restrict__ sc, const float* __restrict__ vh,
                        float* __restrict__ part)
{
    __shared__ float p[16][132];
    __shared__ float vt[128][65];
    const int h = blockIdx.x, b = blockIdx.y, jz = blockIdx.z;
    const int j0 = jz * 128;
    const int tid = threadIdx.x;

#pragma unroll
    for (int q = 0; q < 2; q++) {
        int idx = tid + q * 256;
        int s = idx >> 5, j4 = (idx & 31) * 4;
        float4 v = *(const float4*)&sc[(((size_t)b * HH + h) * NS + s) * LL + j0 + j4];
        *(float4*)&p[s][j4] = v;
    }
#pragma unroll
    for (int q = 0; q < 8; q++) {
        int idx = tid + q * 256;
        int jj = idx >> 4, d4 = (idx & 15) * 4;
        float4 v = *(const float4*)&vh[((size_t)b * LL + j0 + jj) * DD + h * DH + d4];
        vt[jj][d4 + 0] = v.x; vt[jj][d4 + 1] = v.y;
        vt[jj][d4 + 2] = v.z; vt[jj][d4 + 3] = v.w;
    }
    __syncthreads();

    float acc[4] = {0.f, 0.f, 0.f, 0.f};
#pragma unroll 4
    for (int jj = 0; jj < 128; jj++) {
#pragma unroll
        for (int k = 0; k < 4; k++) {
            int idx = tid + k * 256;
            int s = idx >> 6, d = idx & 63;
            acc[k] += p[s][jj] * vt[jj][d];
        }
    }
#pragma unroll
    for (int k = 0; k < 4; k++) {
        int idx = tid + k * 256;
        int s = idx >> 6, d = idx & 63;
        part[(size_t)jz * (BB * NS * DD) + ((size_t)b * NS + s) * DD + h * DH + d] = acc[k];
    }
}

__global__ void disp_reduce(const float* __restrict__ part, float* __restrict__ att1)
{
    int i = blockIdx.x * 256 + threadIdx.x;
    float s = 0.f;
#pragma unroll
    for (int z = 0; z < 16; z++) s += part[(size_t)z * (BB * NS * DD) + i];
    att1[i] = s;
}

// ---------------- layernorm ----------------
__global__ void ln_kernel(const float* __restrict__ inp, const float* __restrict__ gam,
                          const float* __restrict__ bet, float* __restrict__ outp)
{
    const int row = blockIdx.x;
    const int e = row & (NS - 1);
    const float* xr = inp + (size_t)row * DD;
    __shared__ float r1[8], r2[8];
    float s1 = 0.f, s2 = 0.f;
    for (int d = threadIdx.x; d < DD; d += 256) {
        float v = xr[d];
        s1 += v; s2 += v * v;
    }
#pragma unroll
    for (int o = 16; o; o >>= 1) {
        s1 += __shfl_xor_sync(0xffffffffu, s1, o);
        s2 += __shfl_xor_sync(0xffffffffu, s2, o);
    }
    int wid = threadIdx.x >> 5, lane = threadIdx.x & 31;
    if (!lane) { r1[wid] = s1; r2[wid] = s2; }
    __syncthreads();
    if (threadIdx.x < 32) {
        s1 = (lane < 8) ? r1[lane] : 0.f;
        s2 = (lane < 8) ? r2[lane] : 0.f;
#pragma unroll
        for (int o = 4; o; o >>= 1) {
            s1 += __shfl_xor_sync(0xffffffffu, s1, o);
            s2 += __shfl_xor_sync(0xffffffffu, s2, o);
        }
        if (!lane) { r1[0] = s1; r2[0] = s2; }
    }
    __syncthreads();
    float mu  = r1[0] * (1.f / DD);
    float var = r2[0] * (1.f / DD) - mu * mu;
    float inv = rsqrtf(var + 1e-5f);
    for (int d = threadIdx.x; d < DD; d += 256)
        outp[(size_t)row * DD + d] = (xr[d] - mu) * inv * gam[(size_t)e * DD + d] + bet[(size_t)e * DD + d];
}

__device__ __forceinline__ float silu_f(float x) { return x / (1.f + __expf(-x)); }

// ---------------- expert up/gate ----------------
__global__ void expert_ug(const float* __restrict__ hn,
                          const float* __restrict__ W1, const float* __restrict__ b1,
                          const float* __restrict__ Wg, const float* __restrict__ bg,
                          float* __restrict__ ug)
{
    const int e = blockIdx.y;
    const int f = blockIdx.x * 128 + threadIdx.x;
    __shared__ float hs[BB][DD];
    for (int i = threadIdx.x; i < BB * DD / 4; i += 128) {
        int b = (i * 4) >> 10, d4 = (i * 4) & 1023;
        *(float4*)&hs[b][d4] = *(const float4*)&hn[((size_t)b * NS + e) * DD + d4];
    }
    __syncthreads();

    const float* w1 = W1 + (size_t)e * DD * FF + f;
    const float* wg = Wg + (size_t)e * DD * FF + f;
    float au[BB] = {0.f, 0.f, 0.f, 0.f};
    float ag[BB] = {0.f, 0.f, 0.f, 0.f};
#pragma unroll 16
    for (int d = 0; d < DD; d++) {
        float w1v = ldcs(&w1[(size_t)d * FF]);
        float wgv = ldcs(&wg[(size_t)d * FF]);
#pragma unroll
        for (int b = 0; b < BB; b++) {
            float hv = hs[b][d];
            au[b] += hv * w1v;
            ag[b] += hv * wgv;
        }
    }
    float bu = b1[(size_t)e * FF + f];
    float bv = bg[(size_t)e * FF + f];
#pragma unroll
    for (int b = 0; b < BB; b++)
        ug[((size_t)b * EE + e) * FF + f] = silu_f(au[b] + bu) * silu_f(ag[b] + bv);
}

// ---------------- expert down: split-F partials ----------------
__global__ void expert_w2p(const float* __restrict__ ug, const float* __restrict__ W2,
                           float* __restrict__ part)
{
    __shared__ float us[BB][512];
    const int e = blockIdx.y, fz = blockIdx.z;
    const int d = blockIdx.x * 128 + threadIdx.x;
    for (int i = threadIdx.x; i < BB * 512 / 4; i += 128) {
        int b = (i * 4) >> 9, f4 = (i * 4) & 511;
        *(float4*)&us[b][f4] = *(const float4*)&ug[((size_t)b * EE + e) * FF + fz * 512 + f4];
    }
    __syncthreads();
    const float* w = W2 + ((size_t)e * FF + fz * 512) * DD + d;
    float acc[BB] = {0.f, 0.f, 0.f, 0.f};
#pragma unroll 16
    for (int f = 0; f < 512; f++) {
        float wv = ldcs(&w[(size_t)f * DD]);
#pragma unroll
        for (int b = 0; b < BB; b++) acc[b] += us[b][f] * wv;
    }
#pragma unroll
    for (int b = 0; b < BB; b++)
        part[(size_t)fz * (BB * EE * DD) + ((size_t)b * EE + e) * DD + d] = acc[b];
}

__global__ void w2_reduce(const float* __restrict__ part, const float* __restrict__ b2,
                          float* __restrict__ o)
{
    int i = blockIdx.x * 256 + threadIdx.x;
    int d = i & 1023;
    int e = (i >> 10) & 15;
    float s = b2[(size_t)e * DD + d];
#pragma unroll
    for (int z = 0; z < 8; z++) s += part[(size_t)z * (BB * EE * DD) + i];
    o[i] += s;
}

// ---------------- combine attention (fp16 output, batch-chunked) ----------------
__global__ void combine_attn(const float* __restrict__ qh, const float* __restrict__ kh,
                             const float* __restrict__ vh, __half* __restrict__ out, int b0)
{
    extern __shared__ float sm[];
    const int PITCH = HH * 65;
    float* qsm = sm;
    float* ksm = sm + 16 * PITCH;
    float* vsm = sm + 32 * PITCH;
    const int b  = blockIdx.y + b0;
    const int t0 = blockIdx.x * 16;
    const int tid = threadIdx.x;

    for (int i = tid; i < NS * DD; i += 256) {
        int r = i >> 10, hd = i & 1023;
        int h = hd >> 6, d = hd & 63;
        int sw = r * PITCH + h * 65 + d;
        ksm[sw] = kh[(size_t)b * NS * DD + i];
        vsm[sw] = vh[(size_t)b * NS * DD + i];
        qsm[sw] = qh[((size_t)b * LL + t0) * DD + i];
    }
    __syncthreads();

    const int tt = tid >> 4;
    const int h  = tid & 15;

    float qreg[DH];
#pragma unroll
    for (int d = 0; d < DH; d++) qreg[d] = qsm[tt * PITCH + h * 65 + d];

    float sco[NS];
    float mx = -1e30f;
#pragma unroll
    for (int s = 0; s < NS; s++) {
        const float* kp = &ksm[s * PITCH + h * 65];
        float dot = 0.f;
#pragma unroll
        for (int d = 0; d < DH; d++) dot += qreg[d] * kp[d];
        dot *= 0.125f;
        sco[s] = dot;
        mx = fmaxf(mx, dot);
    }
    float sum = 0.f;
#pragma unroll
    for (int s = 0; s < NS; s++) { sco[s] = __expf(sco[s] - mx); sum += sco[s]; }
    float inv = 1.f / sum;

    float ov[DH];
#pragma unroll
    for (int d = 0; d < DH; d++) ov[d] = 0.f;
#pragma unroll
    for (int s = 0; s < NS; s++) {
        float pr = sco[s] * inv;
        const float* vp = &vsm[s * PITCH + h * 65];
#pragma unroll
        for (int d = 0; d < DH; d++) ov[d] += pr * vp[d];
    }
    __syncthreads();
#pragma unroll
    for (int d = 0; d < DH; d++) qsm[tt * PITCH + h * 65 + d] = ov[d];
    __syncthreads();
    for (int i = tid; i < NS * DD; i += 256) {
        int r = i >> 10, hd = i & 1023;
        int hh = hd >> 6, d = hd & 63;
        out[((size_t)b * LL + t0) * DD + i] = __float2half(qsm[r * PITCH + hh * 65 + d]);
    }
}

// ---------------- host launch ----------------
extern "C" void kernel_launch(void* const* d_in, const int* in_sizes, int n_in,
                              void* d_out, int out_size)
{
    const float* x    = (const float*)d_in[0];
    const float* sq   = (const float*)d_in[1];
    const float* dWq  = (const float*)d_in[2];
    const float* dWk  = (const float*)d_in[3];
    const float* dWv  = (const float*)d_in[4];
    const float* dWo  = (const float*)d_in[5];
    const float* dbq  = (const float*)d_in[6];
    const float* dbk  = (const float*)d_in[7];
    const float* dbv  = (const float*)d_in[8];
    const float* dbo  = (const float*)d_in[9];
    const float* cWq  = (const float*)d_in[10];
    const float* cWk  = (const float*)d_in[11];
    const float* cWv  = (const float*)d_in[12];
    const float* cWo  = (const float*)d_in[13];
    const float* cbq  = (const float*)d_in[14];
    const float* cbk  = (const float*)d_in[15];
    const float* cbv  = (const float*)d_in[16];
    const float* cbo  = (const float*)d_in[17];
    const float* elng = (const float*)d_in[18];
    const float* elnb = (const float*)d_in[19];
    const float* eW1  = (const float*)d_in[20];
    const float* eb1  = (const float*)d_in[21];
    const float* eWg  = (const float*)d_in[22];
    const float* ebg  = (const float*)d_in[23];
    const float* eW2  = (const float*)d_in[24];
    const float* eb2  = (const float*)d_in[25];
    float* out = (float*)d_out;

    float *kh, *vh, *qh1, *att1, *o, *hn, *ug, *qh2, *kh2, *vh2;
    float *sc, *avp, *skp, *w2p;
    __half *xh, *wh, *a2h;
    cudaGetSymbolAddress((void**)&kh,   g_kh);
    cudaGetSymbolAddress((void**)&vh,   g_vh);
    cudaGetSymbolAddress((void**)&qh1,  g_qh1);
    cudaGetSymbolAddress((void**)&att1, g_att1);
    cudaGetSymbolAddress((void**)&o,    g_o);
    cudaGetSymbolAddress((void**)&hn,   g_hn);
    cudaGetSymbolAddress((void**)&ug,   g_ug);
    cudaGetSymbolAddress((void**)&qh2,  g_qh2);
    cudaGetSymbolAddress((void**)&kh2,  g_kh2);
    cudaGetSymbolAddress((void**)&vh2,  g_vh2);
    cudaGetSymbolAddress((void**)&sc,   g_sc);
    cudaGetSymbolAddress((void**)&avp,  g_part);
    cudaGetSymbolAddress((void**)&skp,  g_skp);
    cudaGetSymbolAddress((void**)&w2p,  g_w2p);
    cudaGetSymbolAddress((void**)&xh,   g_xh);
    cudaGetSymbolAddress((void**)&wh,   g_wh);
    cudaGetSymbolAddress((void**)&a2h,  g_a2h);

    static cudaStream_t s2 = nullptr;
    static cudaEvent_t ev0, evKH, evVH, evQH2, evPipe, evTail;
    if (!s2) {
        cudaStreamCreateWithFlags(&s2, cudaStreamNonBlocking);
        cudaEventCreateWithFlags(&ev0,   cudaEventDisableTiming);
        cudaEventCreateWithFlags(&evKH,  cudaEventDisableTiming);
        cudaEventCreateWithFlags(&evVH,  cudaEventDisableTiming);
        cudaEventCreateWithFlags(&evQH2, cudaEventDisableTiming);
        cudaEventCreateWithFlags(&evPipe,cudaEventDisableTiming);
        cudaEventCreateWithFlags(&evTail,cudaEventDisableTiming);
    }

    const int SMEM_COMB = 3 * 16 * (HH * 65) * 4;
    cudaFuncSetAttribute(combine_attn, cudaFuncAttributeMaxDynamicSharedMemorySize, SMEM_COMB);
    cudaFuncSetAttribute(gemm_f16, cudaFuncAttributeMaxDynamicSharedMemorySize, GEMM_SMEM_H);

    dim3 gBig(DD / 128, (BB * LL) / 128);     // (8, 64)
    dim3 gHalf(DD / 128, (2 * LL) / 128);     // (8, 32) per 2-batch chunk
    dim3 gSk(DD / 64, 8);
    const int W4 = DD * DD / 4;
    const int X4 = BB * LL * DD / 4;

    cudaEventRecord(ev0, 0);

    // L: conversions then serial fp16 GEMM chain (kh first)
    cvt_f16<<<X4 / 256, 256>>>(x, xh, X4);                                         // 1
    cvt_w4_f16<<<dim3(W4 / 256, 4), 256>>>(dWk, dWv, cWq, cWo, wh);                // 2

    // s2: dispatch Q projection (independent)
    cudaStreamWaitEvent(s2, ev0, 0);
    gemm_skinny<16><<<gSk, 256, 0, s2>>>(sq, dWq, skp, DD, DD);                    // 3

    gemm_f16<<<gBig, 256, GEMM_SMEM_H>>>(xh, wh + 0 * DD * DD, dbk, kh, BB * LL, DD, DD);  // 4
    cudaEventRecord(evKH, 0);

    skinny_reduce<<<(16 * DD) / 256, 256, 0, s2>>>(skp, dbq, qh1, 16, DD);

    gemm_f16<<<gBig, 256, GEMM_SMEM_H>>>(xh, wh + 1 * DD * DD, dbv, vh, BB * LL, DD, DD);
    cudaEventRecord(evVH, 0);
    gemm_f16<<<gBig, 256, GEMM_SMEM_H>>>(xh, wh + 2 * DD * DD, cbq, qh2, BB * LL, DD, DD);
    cudaEventRecord(evQH2, 0);

    // s2: dispatch attention -> experts -> combine projections
    cudaStreamWaitEvent(s2, evKH, 0);
    disp_scores<<<dim3(LL / 128, HH, BB), 256, 0, s2>>>(qh1, kh, sc);
    disp_softmax<<<BB * HH * NS, 256, 0, s2>>>(sc);
    cudaStreamWaitEvent(s2, evVH, 0);
    disp_av<<<dim3(HH, BB, 16), 256, 0, s2>>>(sc, vh, avp);
    disp_reduce<<<(BB * NS * DD) / 256, 256, 0, s2>>>(avp, att1);

    gemm_skinny<64><<<gSk, 256, 0, s2>>>(att1, dWo, skp, DD, DD);
    skinny_reduce_addsq<<<(64 * DD) / 256, 256, 0, s2>>>(skp, dbo, sq, o);

    ln_kernel<<<BB * NS, 256, 0, s2>>>(o, elng, elnb, hn);
    expert_ug<<<dim3(FF / 128, EE), 128, 0, s2>>>(hn, eW1, eb1, eWg, ebg, ug);
    expert_w2p<<<dim3(DD / 128, EE, 8), 128, 0, s2>>>(ug, eW2, w2p);
    w2_reduce<<<(BB * EE * DD) / 256, 256, 0, s2>>>(w2p, eb2, o);

    gemm_skinny_dual<<<dim3(DD / 64, 8, 2), 256, 0, s2>>>(o, cWk, cWv, skp, w2p);
    skinny_reduce_dual<<<dim3((64 * DD) / 256, 2), 256, 0, s2>>>(skp, w2p, cbk, cbv, kh2, vh2);
    cudaEventRecord(evPipe, s2);

    // ---- tail: split combine + final GEMM into two 2-batch chunks on 2 streams ----
    // s2 chunk: batches 2..3 (needs qh2 from L)
    cudaStreamWaitEvent(s2, evQH2, 0);
    combine_attn<<<dim3(LL / 16, 2), 256, SMEM_COMB, s2>>>(qh2, kh2, vh2, a2h, 2);
    gemm_f16<<<gHalf, 256, GEMM_SMEM_H, s2>>>(a2h + (size_t)2 * LL * DD, wh + 3 * DD * DD,
                                              cbo, out + (size_t)2 * LL * DD, 2 * LL, DD, DD);
    cudaEventRecord(evTail, s2);

    // L chunk: batches 0..1 (needs kh2/vh2 from s2)
    cudaStreamWaitEvent(0, evPipe, 0);
    combine_attn<<<dim3(LL / 16, 2), 256, SMEM_COMB>>>(qh2, kh2, vh2, a2h, 0);
    gemm_f16<<<gHalf, 256, GEMM_SMEM_H>>>(a2h, wh + 3 * DD * DD, cbo, out, 2 * LL, DD, DD);

    // join s2 back into L so the captured graph includes the s2 tail
    cudaStreamWaitEvent(0, evTail, 0);
}